// round 11
// baseline (speedup 1.0000x reference)
#include <cuda_runtime.h>
#include <cuda_bf16.h>
#include <cstdint>

#define B_TOT 65536

// Scratch (device globals = sanctioned scratch path)
__device__ float g_ea [(size_t)B_TOT * 256];   // exp(attn logits) [b][c][d]
__device__ float g_val[(size_t)B_TOT * 512];   // value [b][c][e]
__device__ float g_sums[256];                  // softmax denominators (then inverses)

typedef unsigned long long ull;

__device__ __forceinline__ ull ffma2(ull a, ull b, ull c) {
    ull d;
    asm("fma.rn.f32x2 %0, %1, %2, %3;" : "=l"(d) : "l"(a), "l"(b), "l"(c));
    return d;
}
__device__ __forceinline__ float usum(ull v) {
    float lo, hi;
    asm("mov.b64 {%0, %1}, %2;" : "=f"(lo), "=f"(hi) : "l"(v));
    return lo + hi;
}
__device__ __forceinline__ void cpa16(unsigned int s, const float* g) {
    asm volatile("cp.async.cg.shared.global [%0], [%1], 16;" :: "r"(s), "l"(g));
}
#define CP_COMMIT()  asm volatile("cp.async.commit_group;")
#define CP_WAIT(n)   asm volatile("cp.async.wait_group %0;" :: "n"(n))

__global__ void k_zero()  { g_sums[threadIdx.x] = 0.0f; }
__global__ void k_dummy() {}
__global__ void k_inv()   { g_sums[threadIdx.x] = 1.0f / g_sums[threadIdx.x]; }

// -------------------------------------------------------------------------
// K1: fused QKV linears + shuffle-free norms + attn logits + exp + sums
// 64 threads = 2 warps, warp-per-PAIR-of-batches, 2 pairs/warp -> 8 batches/blk
// Two batches interleaved through the QKV loop (12 indep acc chains) so the
// warp has 2x independent work in every latency window. Weights in registers.
// -------------------------------------------------------------------------
__global__ void __launch_bounds__(64) k1(
    const float* __restrict__ e1g, const float* __restrict__ e2g,
    const float* __restrict__ qW, const float* __restrict__ qb,
    const float* __restrict__ kW, const float* __restrict__ kb,
    const float* __restrict__ vW, const float* __restrict__ vb)
{
    // per-warp: 2 X buffers (one per batch of the pair): e1(512)+e2(512) each
    __shared__ __align__(16) float xb[2][2][1024];            // 16 KB
    // per-warp, per-batch-in-pair: q(576,pad36) k(576) invn(32)
    __shared__ __align__(16) float qk[2][2][1184];            // 18.9 KB
    __shared__ float s_sums[256];                             // 1 KB

    const int tid = threadIdx.x, warp = tid >> 5, lane = tid & 31;
    for (int i = tid; i < 256; i += 64) s_sums[i] = 0.0f;
    __syncthreads();

    float* w0 = xb[warp][0];
    float* w1 = xb[warp][1];
    float* t0 = qk[warp][0];   // qns0=t0, kns0=t0+576, invn0=t0+1152
    float* t1 = qk[warp][1];

    // attn tile ownership: lane -> rows c0,c0+1 x cols d0..d0+3
    const int c0 = (lane >> 2) * 2;
    const int d0 = (lane & 3) * 4;

    // ---- hoist weights: 48 ull regs, loaded ONCE ----
    ull wq[16], wk[16], wv[16];
    {
        const ull* qg = (const ull*)(qW + lane * 32);
        const ull* kg = (const ull*)(kW + lane * 32);
        const ull* vg = (const ull*)(vW + lane * 32);
#pragma unroll
        for (int j = 0; j < 16; j++) { wq[j] = qg[j]; wk[j] = kg[j]; wv[j] = vg[j]; }
    }
    const float bq = qb[lane], bk = kb[lane], bv = vb[lane];

    float sacc[8];
#pragma unroll
    for (int t = 0; t < 8; t++) sacc[t] = 0.0f;

    const int b_base = blockIdx.x * 8 + warp * 4;   // 4 batches per warp (2 pairs)

    const unsigned int sxA = (unsigned int)__cvta_generic_to_shared(w0) + lane * 16;
    const unsigned int sxB = (unsigned int)__cvta_generic_to_shared(w1) + lane * 16;

    // prologue: prefetch pair 0 (batches b_base, b_base+1)
    {
        const float* E1a = e1g + (size_t)b_base * 512 + lane * 4;
        const float* E2a = e2g + (size_t)b_base * 512 + lane * 4;
        const float* E1b = e1g + (size_t)(b_base + 1) * 512 + lane * 4;
        const float* E2b = e2g + (size_t)(b_base + 1) * 512 + lane * 4;
#pragma unroll
        for (int r = 0; r < 4; r++) {
            cpa16(sxA + r * 512,        E1a + r * 128);
            cpa16(sxA + 2048 + r * 512, E2a + r * 128);
            cpa16(sxB + r * 512,        E1b + r * 128);
            cpa16(sxB + 2048 + r * 512, E2b + r * 128);
        }
    }
    CP_COMMIT();

#pragma unroll 1
    for (int p = 0; p < 2; p++) {
        const int b0 = b_base + 2 * p;
        const int b1 = b0 + 1;

        CP_WAIT(0);
        __syncwarp();   // pair's X tiles complete & visible

        const ulonglong2* e1A = (const ulonglong2*)w0;
        const ulonglong2* e2A = (const ulonglong2*)(w0 + 512);
        const ulonglong2* e1B = (const ulonglong2*)w1;
        const ulonglong2* e2B = (const ulonglong2*)(w1 + 512);

        float* voutA = g_val + (size_t)b0 * 512;
        float* voutB = g_val + (size_t)b1 * 512;

        // ---- fused Q/K/V for BOTH batches interleaved: 12 indep chains ----
#pragma unroll 1
        for (int c = 0; c < 16; c++) {
            ull a1q=0,a2q=0,a1k=0,a2k=0,a1v=0,a2v=0;     // batch0
            ull g1q=0,g2q=0,g1k=0,g2k=0,g1v=0,g2v=0;     // batch1
#pragma unroll
            for (int j = 0; j < 8; j++) {
                ulonglong2 xA = e1A[c * 8 + j];
                ulonglong2 yA = e2A[c * 8 + j];
                ulonglong2 xB = e1B[c * 8 + j];
                ulonglong2 yB = e2B[c * 8 + j];
                a1q = ffma2(xA.x, wq[2*j], a1q); a1q = ffma2(xA.y, wq[2*j+1], a1q);
                g1q = ffma2(xB.x, wq[2*j], g1q); g1q = ffma2(xB.y, wq[2*j+1], g1q);
                a2q = ffma2(yA.x, wq[2*j], a2q); a2q = ffma2(yA.y, wq[2*j+1], a2q);
                g2q = ffma2(yB.x, wq[2*j], g2q); g2q = ffma2(yB.y, wq[2*j+1], g2q);
                a1k = ffma2(xA.x, wk[2*j], a1k); a1k = ffma2(xA.y, wk[2*j+1], a1k);
                g1k = ffma2(xB.x, wk[2*j], g1k); g1k = ffma2(xB.y, wk[2*j+1], g1k);
                a2k = ffma2(yA.x, wk[2*j], a2k); a2k = ffma2(yA.y, wk[2*j+1], a2k);
                g2k = ffma2(yB.x, wk[2*j], g2k); g2k = ffma2(yB.y, wk[2*j+1], g2k);
                a1v = ffma2(xA.x, wv[2*j], a1v); a1v = ffma2(xA.y, wv[2*j+1], a1v);
                g1v = ffma2(xB.x, wv[2*j], g1v); g1v = ffma2(xB.y, wv[2*j+1], g1v);
                a2v = ffma2(yA.x, wv[2*j], a2v); a2v = ffma2(yA.y, wv[2*j+1], a2v);
                g2v = ffma2(yB.x, wv[2*j], g2v); g2v = ffma2(yB.y, wv[2*j+1], g2v);
            }
            t0[c * 36 + lane]       = (usum(a1q) + bq) * (usum(a2q) + bq);
            t1[c * 36 + lane]       = (usum(g1q) + bq) * (usum(g2q) + bq);
            t0[576 + c * 36 + lane] = (usum(a1k) + bk) * (usum(a2k) + bk);
            t1[576 + c * 36 + lane] = (usum(g1k) + bk) * (usum(g2k) + bk);
            voutA[c * 32 + lane]    = (usum(a1v) + bv) * (usum(a2v) + bv);
            voutB[c * 32 + lane]    = (usum(g1v) + bv) * (usum(g2v) + bv);
        }
        __syncwarp();   // qk tiles written; X buffers now free

        // prefetch next pair into the SAME buffers — overlaps norms+attn
        if (p == 0) {
            const float* E1a = e1g + (size_t)(b_base + 2) * 512 + lane * 4;
            const float* E2a = e2g + (size_t)(b_base + 2) * 512 + lane * 4;
            const float* E1b = e1g + (size_t)(b_base + 3) * 512 + lane * 4;
            const float* E2b = e2g + (size_t)(b_base + 3) * 512 + lane * 4;
#pragma unroll
            for (int r = 0; r < 4; r++) {
                cpa16(sxA + r * 512,        E1a + r * 128);
                cpa16(sxA + 2048 + r * 512, E2a + r * 128);
                cpa16(sxB + r * 512,        E1b + r * 128);
                cpa16(sxB + 2048 + r * 512, E2b + r * 128);
            }
        }
        CP_COMMIT();

        // ---- shuffle-free row norms, both batches interleaved ----
        {
            const int r = lane & 15;
            const ulonglong2* rp0 = (const ulonglong2*)((lane < 16 ? t0 : t0 + 576) + r * 36);
            const ulonglong2* rp1 = (const ulonglong2*)((lane < 16 ? t1 : t1 + 576) + r * 36);
            ull a0 = 0ull, a1n = 0ull;
#pragma unroll
            for (int j = 0; j < 8; j++) {
                ulonglong2 x0 = rp0[j], x1 = rp1[j];
                a0  = ffma2(x0.x, x0.x, a0);  a0  = ffma2(x0.y, x0.y, a0);
                a1n = ffma2(x1.x, x1.x, a1n); a1n = ffma2(x1.y, x1.y, a1n);
            }
            // ref: x / max(||x||, 1e-12)  ->  scale = rsqrt(max(sum, 1e-24))
            t0[1152 + lane] = rsqrtf(fmaxf(usum(a0),  1e-24f));
            t1[1152 + lane] = rsqrtf(fmaxf(usum(a1n), 1e-24f));
        }
        __syncwarp();

        // ---- attn per batch: attn[c][d] = (q[c].k[d])*invq[c]*invk[d] ----
#pragma unroll 1
        for (int s = 0; s < 2; s++) {
            float* t = s ? t1 : t0;
            const int bb = s ? b1 : b0;

            ull acc[8];
#pragma unroll
            for (int u = 0; u < 8; u++) acc[u] = 0ull;
            const ulonglong2* qv = (const ulonglong2*)t;          // 9 u64x2/row
            const ulonglong2* kv = (const ulonglong2*)(t + 576);
#pragma unroll
            for (int j = 0; j < 8; j++) {
                ulonglong2 qa  = qv[c0 * 9 + j];
                ulonglong2 qc2 = qv[(c0 + 1) * 9 + j];
#pragma unroll
                for (int jj = 0; jj < 4; jj++) {
                    ulonglong2 kt = kv[(d0 + jj) * 9 + j];
                    acc[jj]     = ffma2(qa.x,  kt.x, acc[jj]);
                    acc[jj]     = ffma2(qa.y,  kt.y, acc[jj]);
                    acc[4 + jj] = ffma2(qc2.x, kt.x, acc[4 + jj]);
                    acc[4 + jj] = ffma2(qc2.y, kt.y, acc[4 + jj]);
                }
            }

            const float* invn = t + 1152;
            const float iq0 = invn[c0], iq1 = invn[c0 + 1];
            float ik[4];
#pragma unroll
            for (int jj = 0; jj < 4; jj++) ik[jj] = invn[16 + d0 + jj];

            float* eaout = g_ea + (size_t)bb * 256;
#pragma unroll
            for (int i = 0; i < 2; i++) {
                const float iq = i ? iq1 : iq0;
#pragma unroll
                for (int jj = 0; jj < 4; jj++) {
                    // cosine logits in [-1,1] -> exp w/o max-subtraction safe
                    float ea = __expf(usum(acc[i * 4 + jj]) * iq * ik[jj]);
                    sacc[i * 4 + jj] += ea;
                    eaout[(c0 + i) * 16 + d0 + jj] = ea;
                }
            }
        }
        __syncwarp();   // qk tiles free for next pair
    }

    // block-level reduction of softmax sums, then one global atomic per slot
#pragma unroll
    for (int i = 0; i < 2; i++)
#pragma unroll
        for (int jj = 0; jj < 4; jj++)
            atomicAdd(&s_sums[(c0 + i) * 16 + d0 + jj], sacc[i * 4 + jj]);
    __syncthreads();
    for (int i = tid; i < 256; i += 64)
        atomicAdd(&g_sums[i], s_sums[i]);
}

// -------------------------------------------------------------------------
// K2: p = ea * inv_sum; out = p^T @ v; MLP 512->48(relu)->3; L2-normalize
// 256 threads = 8 warps, 8 batches/block
// -------------------------------------------------------------------------
__global__ void __launch_bounds__(256, 3) k2(
    const float* __restrict__ p1W, const float* __restrict__ p1b,
    const float* __restrict__ p2W, const float* __restrict__ p2b,
    float* __restrict__ out)
{
    __shared__ float s_inv[256];
    __shared__ __align__(16) float p_s[8][256];
    __shared__ __align__(16) float h_s[8][512];
    __shared__ float y_s[8][48];
    __shared__ float z_s[8][3];

    const int tid = threadIdx.x, warp = tid >> 5, lane = tid & 31;
    s_inv[tid] = g_sums[tid];   // already inverted by k_inv
    __syncthreads();

    // ---- phase A: per-warp batch: p and out = attn^T @ value -> h_s ----
    {
        const int b = blockIdx.x * 8 + warp;
        const float* eain = g_ea + (size_t)b * 256;
#pragma unroll
        for (int i = 0; i < 8; i++)
            p_s[warp][i * 32 + lane] = eain[i * 32 + lane] * s_inv[i * 32 + lane];

        float v[16];
        const float* vin = g_val + (size_t)b * 512;
#pragma unroll
        for (int c = 0; c < 16; c++) v[c] = vin[c * 32 + lane];
        __syncwarp();

#pragma unroll
        for (int d = 0; d < 16; d++) {
            float acc = 0.0f;
#pragma unroll
            for (int c = 0; c < 16; c++)
                acc = fmaf(p_s[warp][c * 16 + d], v[c], acc);   // broadcast LDS
            h_s[warp][d * 32 + lane] = acc;                     // h[b][d*32+e]
        }
    }
    __syncthreads();

    // ---- phase B: Y[8][48] = H[8][512] @ W1^T, register-blocked r=8,c=3 ----
    {
        const int g = tid >> 4, sub = tid & 15;   // 16 groups x 16 subs
        ull acc[8][3];
#pragma unroll
        for (int r = 0; r < 8; r++) { acc[r][0] = 0; acc[r][1] = 0; acc[r][2] = 0; }

        const ull* w0 = (const ull*)(p1W + (size_t)(g     ) * 512);
        const ull* w1 = (const ull*)(p1W + (size_t)(g + 16) * 512);
        const ull* w2 = (const ull*)(p1W + (size_t)(g + 32) * 512);

#pragma unroll
        for (int t = 0; t < 16; t++) {
            const int iw = sub + 16 * t;          // conflict-free
            ull a0 = w0[iw], a1 = w1[iw], a2 = w2[iw];
#pragma unroll
            for (int r = 0; r < 8; r++) {
                ull hv = *(const ull*)(&h_s[r][2 * sub + 32 * t]);
                acc[r][0] = ffma2(hv, a0, acc[r][0]);
                acc[r][1] = ffma2(hv, a1, acc[r][1]);
                acc[r][2] = ffma2(hv, a2, acc[r][2]);
            }
        }
#pragma unroll
        for (int r = 0; r < 8; r++)
#pragma unroll
            for (int m = 0; m < 3; m++) {
                float p = usum(acc[r][m]);
#pragma unroll
                for (int o = 8; o > 0; o >>= 1)
                    p += __shfl_down_sync(0xffffffffu, p, o, 16);
                if (sub == 0) {
                    const int j = g + 16 * m;
                    y_s[r][j] = fmaxf(p + p1b[j], 0.0f);   // relu
                }
            }
    }
    __syncthreads();

    // ---- phase C: layer 2 (24 threads: one (batch,m) pair each) ----
    if (tid < 24) {
        const int rb = tid / 3, m = tid % 3;
        float a = p2b[m];
#pragma unroll
        for (int j = 0; j < 48; j++)
            a = fmaf(y_s[rb][j], p2W[m * 48 + j], a);
        z_s[rb][m] = a;
    }
    __syncthreads();

    // ---- L2 normalize + write ----
    if (tid < 8) {
        float z0 = z_s[tid][0], z1 = z_s[tid][1], z2 = z_s[tid][2];
        float n = sqrtf(z0 * z0 + z1 * z1 + z2 * z2);
        float inv = 1.0f / fmaxf(n, 1e-12f);
        const size_t b = (size_t)blockIdx.x * 8 + tid;
        out[b * 3 + 0] = z0 * inv;
        out[b * 3 + 1] = z1 * inv;
        out[b * 3 + 2] = z2 * inv;
    }
}

extern "C" void kernel_launch(void* const* d_in, const int* in_sizes, int n_in,
                              void* d_out, int out_size)
{
    const float* e1  = (const float*)d_in[0];
    const float* e2  = (const float*)d_in[1];
    const float* qW  = (const float*)d_in[2];
    const float* qb  = (const float*)d_in[3];
    const float* kW  = (const float*)d_in[4];
    const float* kb  = (const float*)d_in[5];
    const float* vW  = (const float*)d_in[6];
    const float* vb  = (const float*)d_in[7];
    const float* p1W = (const float*)d_in[8];
    const float* p1b = (const float*)d_in[9];
    const float* p2W = (const float*)d_in[10];
    const float* p2b = (const float*)d_in[11];
    float* out = (float*)d_out;

    k_zero<<<1, 256>>>();
    // two no-op launches to steer ncu's (-s 5 -c 1) capture window onto k1
    k_dummy<<<1, 32>>>();
    k_dummy<<<1, 32>>>();
    k1<<<B_TOT / 8, 64>>>(e1, e2, qW, qb, kW, kb, vW, vb);
    k_inv<<<1, 256>>>();
    k2<<<B_TOT / 8, 256>>>(p1W, p1b, p2W, p2b, out);
}

// round 12
// speedup vs baseline: 1.0685x; 1.0685x over previous
#include <cuda_runtime.h>
#include <cuda_bf16.h>
#include <cstdint>

#define B_TOT 65536

// Scratch (device globals = sanctioned scratch path)
__device__ float g_ea [(size_t)B_TOT * 256];   // exp(attn logits) [b][c][d]
__device__ float g_val[(size_t)B_TOT * 512];   // value [b][c][e]
__device__ float g_sums[256];                  // softmax denominators (then inverses)

typedef unsigned long long ull;

__device__ __forceinline__ ull ffma2(ull a, ull b, ull c) {
    ull d;
    asm("fma.rn.f32x2 %0, %1, %2, %3;" : "=l"(d) : "l"(a), "l"(b), "l"(c));
    return d;
}
__device__ __forceinline__ float usum(ull v) {
    float lo, hi;
    asm("mov.b64 {%0, %1}, %2;" : "=f"(lo), "=f"(hi) : "l"(v));
    return lo + hi;
}
__device__ __forceinline__ ull pk(float lo, float hi) {
    ull r;
    asm("mov.b64 %0, {%1, %2};" : "=l"(r) : "f"(lo), "f"(hi));
    return r;
}
__device__ __forceinline__ void upk(ull v, float& lo, float& hi) {
    asm("mov.b64 {%0, %1}, %2;" : "=f"(lo), "=f"(hi) : "l"(v));
}
__device__ __forceinline__ ull addf2(ull a, ull b) {
    ull r;
    asm("add.rn.f32x2 %0, %1, %2;" : "=l"(r) : "l"(a), "l"(b));
    return r;
}
__device__ __forceinline__ unsigned tf32(float f) {
    unsigned r;
    asm("cvt.rna.tf32.f32 %0, %1;" : "=r"(r) : "f"(f));
    return r;
}
__device__ __forceinline__ void mma_tf32(float* c, const unsigned* a, const unsigned* b) {
    asm volatile(
        "mma.sync.aligned.m16n8k8.row.col.f32.tf32.tf32.f32 "
        "{%0,%1,%2,%3}, {%4,%5,%6,%7}, {%8,%9}, {%0,%1,%2,%3};"
        : "+f"(c[0]), "+f"(c[1]), "+f"(c[2]), "+f"(c[3])
        : "r"(a[0]), "r"(a[1]), "r"(a[2]), "r"(a[3]), "r"(b[0]), "r"(b[1]));
}
__device__ __forceinline__ void cpa16(unsigned int s, const float* g) {
    asm volatile("cp.async.cg.shared.global [%0], [%1], 16;" :: "r"(s), "l"(g));
}
#define CP_COMMIT()  asm volatile("cp.async.commit_group;")
#define CP_WAIT(n)   asm volatile("cp.async.wait_group %0;" :: "n"(n))

__global__ void k_zero()  { g_sums[threadIdx.x] = 0.0f; }
__global__ void k_dummy() {}
__global__ void k_inv()   { g_sums[threadIdx.x] = 1.0f / g_sums[threadIdx.x]; }

// -------------------------------------------------------------------------
// K1: Q,K via tf32 tensor-core mma (A-frags from pitch-36 smem X tiles,
// W-frags in regs); V exact fp32 ffma2; norms from mma epilogue; attn fp32.
// 96 threads = 3 warps, warp-per-batch, 4 batches/warp -> 12 batches/block.
// -------------------------------------------------------------------------
__global__ void __launch_bounds__(96, 3) k1(
    const float* __restrict__ e1g, const float* __restrict__ e2g,
    const float* __restrict__ qW, const float* __restrict__ qb,
    const float* __restrict__ kW, const float* __restrict__ kb,
    const float* __restrict__ vW, const float* __restrict__ vb)
{
    // per-warp: 2 X buffers, each e1(16x36=576) + e2(576), pitch-36 rows
    __shared__ __align__(16) float xbuf[3][2][1152];          // 27.6 KB
    // per-warp: q(576,pad36) k(576,pad36) invn(32)
    __shared__ __align__(16) float qkbuf[3][1184];            // 14.2 KB
    __shared__ float s_sums[256];                             // 1 KB

    const int tid = threadIdx.x, warp = tid / 32, lane = tid & 31;
    for (int i = tid; i < 256; i += 96) s_sums[i] = 0.0f;
    __syncthreads();

    float* qns  = qkbuf[warp];          // RAW q, 16 rows, pitch 36
    float* kns  = qns + 576;            // RAW k
    float* invn = kns + 576;            // [0..15]=1/||q||, [16..31]=1/||k||

    const int g = lane >> 2, t = lane & 3;    // mma fragment coords

    // attn tile ownership: lane -> rows c0,c0+1 x cols d0..d0+3
    const int c0 = (lane >> 2) * 2;
    const int d0 = (lane & 3) * 4;

    // ---- preload W fragments (tf32) for Q and K: [nc][kc][2] ----
    unsigned bqf[4][4][2], bkf[4][4][2];
#pragma unroll
    for (int nc = 0; nc < 4; nc++)
#pragma unroll
        for (int kc = 0; kc < 4; kc++) {
            const int row = 8 * nc + g, col = 8 * kc + t;
            bqf[nc][kc][0] = tf32(qW[row * 32 + col]);
            bqf[nc][kc][1] = tf32(qW[row * 32 + col + 4]);
            bkf[nc][kc][0] = tf32(kW[row * 32 + col]);
            bkf[nc][kc][1] = tf32(kW[row * 32 + col + 4]);
        }
    // biases in accumulator-column layout: cols 8nc+2t, 8nc+2t+1
    float bq0[4], bq1[4], bk0[4], bk1[4];
#pragma unroll
    for (int nc = 0; nc < 4; nc++) {
        bq0[nc] = qb[8 * nc + 2 * t]; bq1[nc] = qb[8 * nc + 2 * t + 1];
        bk0[nc] = kb[8 * nc + 2 * t]; bk1[nc] = kb[8 * nc + 2 * t + 1];
    }
    // V weights (exact fp32 path)
    ull wv[16];
    {
        const ull* vg = (const ull*)(vW + lane * 32);
#pragma unroll
        for (int j = 0; j < 16; j++) wv[j] = vg[j];
    }
    const float bv = vb[lane];

    float sacc[8];
#pragma unroll
    for (int u = 0; u < 8; u++) sacc[u] = 0.0f;

    const int b_base = blockIdx.x * 12 + warp * 4;

    const unsigned sb0 = (unsigned)__cvta_generic_to_shared(&xbuf[warp][0][0]);
    const unsigned sb1 = (unsigned)__cvta_generic_to_shared(&xbuf[warp][1][0]);
    const int prow = (lane >> 3);           // cp.async dest row base
    const int pcol = (lane & 7) * 16;       // byte offset within row

    // prologue: prefetch batch 0 (pitch-36 destination)
    if (b_base < B_TOT) {
        const float* E1 = e1g + (size_t)b_base * 512 + lane * 4;
        const float* E2 = e2g + (size_t)b_base * 512 + lane * 4;
#pragma unroll
        for (int r = 0; r < 4; r++) {
            const unsigned d = sb0 + (prow + 4 * r) * 144 + pcol;
            cpa16(d,        E1 + r * 128);
            cpa16(d + 2304, E2 + r * 128);
        }
    }
    CP_COMMIT();

#pragma unroll 1
    for (int ib = 0; ib < 4; ib++) {
        const int b = b_base + ib;
        const bool valid = (b < B_TOT);

        // prefetch next batch into the other buffer
        if (ib < 3 && b + 1 < B_TOT) {
            const unsigned sx = (ib & 1) ? sb0 : sb1;
            const float* E1 = e1g + (size_t)(b + 1) * 512 + lane * 4;
            const float* E2 = e2g + (size_t)(b + 1) * 512 + lane * 4;
#pragma unroll
            for (int r = 0; r < 4; r++) {
                const unsigned d = sx + (prow + 4 * r) * 144 + pcol;
                cpa16(d,        E1 + r * 128);
                cpa16(d + 2304, E2 + r * 128);
            }
        }
        CP_COMMIT();
        if (ib < 3) { CP_WAIT(1); } else { CP_WAIT(0); }
        __syncwarp();   // current buffer complete & visible

        if (valid) {
            const float* w = xbuf[warp][ib & 1];        // e1 tile (pitch 36)
            const float* w2 = w + 576;                  // e2 tile

            // ---- V pass: exact fp32, per-lane feature e = lane ----
            {
                float* vout = g_val + (size_t)b * 512;
#pragma unroll 2
                for (int c = 0; c < 16; c++) {
                    const ulonglong2* x1 = (const ulonglong2*)(w + c * 36);
                    const ulonglong2* x2 = (const ulonglong2*)(w2 + c * 36);
                    ull a1 = 0ull, a2 = 0ull;
#pragma unroll
                    for (int j = 0; j < 4; j++) {
                        ulonglong2 xa = x1[j], ya = x2[j];
                        a1 = ffma2(xa.x, wv[2*j],   a1); a1 = ffma2(xa.y, wv[2*j+1], a1);
                        a2 = ffma2(ya.x, wv[2*j],   a2); a2 = ffma2(ya.y, wv[2*j+1], a2);
                    }
#pragma unroll
                    for (int j = 4; j < 8; j++) {
                        ulonglong2 xa = x1[j], ya = x2[j];
                        a1 = ffma2(xa.x, wv[2*j],   a1); a1 = ffma2(xa.y, wv[2*j+1], a1);
                        a2 = ffma2(ya.x, wv[2*j],   a2); a2 = ffma2(ya.y, wv[2*j+1], a2);
                    }
                    vout[c * 32 + lane] = (usum(a1) + bv) * (usum(a2) + bv);
                }
            }

            // ---- Q phase: tensor-core mma over both embeds ----
            {
                float qA[4][4], qB[4][4];
#pragma unroll
                for (int nc = 0; nc < 4; nc++)
#pragma unroll
                    for (int r = 0; r < 4; r++) { qA[nc][r] = 0.0f; qB[nc][r] = 0.0f; }
#pragma unroll
                for (int kc = 0; kc < 4; kc++) {
                    unsigned a1[4], a2[4];
                    const int cb = 8 * kc + t;
                    a1[0] = tf32(w[g * 36 + cb]);        a1[1] = tf32(w[(g + 8) * 36 + cb]);
                    a1[2] = tf32(w[g * 36 + cb + 4]);    a1[3] = tf32(w[(g + 8) * 36 + cb + 4]);
                    a2[0] = tf32(w2[g * 36 + cb]);       a2[1] = tf32(w2[(g + 8) * 36 + cb]);
                    a2[2] = tf32(w2[g * 36 + cb + 4]);   a2[3] = tf32(w2[(g + 8) * 36 + cb + 4]);
#pragma unroll
                    for (int nc = 0; nc < 4; nc++) {
                        mma_tf32(qA[nc], a1, bqf[nc][kc]);
                        mma_tf32(qB[nc], a2, bqf[nc][kc]);
                    }
                }
                float slo = 0.0f, shi = 0.0f;
#pragma unroll
                for (int nc = 0; nc < 4; nc++) {
                    float v0 = (qA[nc][0] + bq0[nc]) * (qB[nc][0] + bq0[nc]);
                    float v1 = (qA[nc][1] + bq1[nc]) * (qB[nc][1] + bq1[nc]);
                    float v2 = (qA[nc][2] + bq0[nc]) * (qB[nc][2] + bq0[nc]);
                    float v3 = (qA[nc][3] + bq1[nc]) * (qB[nc][3] + bq1[nc]);
                    *(float2*)(qns + g * 36 + 8 * nc + 2 * t)       = make_float2(v0, v1);
                    *(float2*)(qns + (g + 8) * 36 + 8 * nc + 2 * t) = make_float2(v2, v3);
                    slo = fmaf(v0, v0, fmaf(v1, v1, slo));
                    shi = fmaf(v2, v2, fmaf(v3, v3, shi));
                }
                ull s = pk(slo, shi);
                s = addf2(s, __shfl_xor_sync(0xffffffffu, s, 1));
                s = addf2(s, __shfl_xor_sync(0xffffffffu, s, 2));
                float rlo, rhi; upk(s, rlo, rhi);
                if (t == 0) {
                    // ref: x / max(||x||,1e-12) -> scale = rsqrt(max(ss,1e-24))
                    invn[g]     = rsqrtf(fmaxf(rlo, 1e-24f));
                    invn[g + 8] = rsqrtf(fmaxf(rhi, 1e-24f));
                }
            }

            // ---- K phase: same pattern ----
            {
                float kA[4][4], kB[4][4];
#pragma unroll
                for (int nc = 0; nc < 4; nc++)
#pragma unroll
                    for (int r = 0; r < 4; r++) { kA[nc][r] = 0.0f; kB[nc][r] = 0.0f; }
#pragma unroll
                for (int kc = 0; kc < 4; kc++) {
                    unsigned a1[4], a2[4];
                    const int cb = 8 * kc + t;
                    a1[0] = tf32(w[g * 36 + cb]);        a1[1] = tf32(w[(g + 8) * 36 + cb]);
                    a1[2] = tf32(w[g * 36 + cb + 4]);    a1[3] = tf32(w[(g + 8) * 36 + cb + 4]);
                    a2[0] = tf32(w2[g * 36 + cb]);       a2[1] = tf32(w2[(g + 8) * 36 + cb]);
                    a2[2] = tf32(w2[g * 36 + cb + 4]);   a2[3] = tf32(w2[(g + 8) * 36 + cb + 4]);
#pragma unroll
                    for (int nc = 0; nc < 4; nc++) {
                        mma_tf32(kA[nc], a1, bkf[nc][kc]);
                        mma_tf32(kB[nc], a2, bkf[nc][kc]);
                    }
                }
                float slo = 0.0f, shi = 0.0f;
#pragma unroll
                for (int nc = 0; nc < 4; nc++) {
                    float v0 = (kA[nc][0] + bk0[nc]) * (kB[nc][0] + bk0[nc]);
                    float v1 = (kA[nc][1] + bk1[nc]) * (kB[nc][1] + bk1[nc]);
                    float v2 = (kA[nc][2] + bk0[nc]) * (kB[nc][2] + bk0[nc]);
                    float v3 = (kA[nc][3] + bk1[nc]) * (kB[nc][3] + bk1[nc]);
                    *(float2*)(kns + g * 36 + 8 * nc + 2 * t)       = make_float2(v0, v1);
                    *(float2*)(kns + (g + 8) * 36 + 8 * nc + 2 * t) = make_float2(v2, v3);
                    slo = fmaf(v0, v0, fmaf(v1, v1, slo));
                    shi = fmaf(v2, v2, fmaf(v3, v3, shi));
                }
                ull s = pk(slo, shi);
                s = addf2(s, __shfl_xor_sync(0xffffffffu, s, 1));
                s = addf2(s, __shfl_xor_sync(0xffffffffu, s, 2));
                float rlo, rhi; upk(s, rlo, rhi);
                if (t == 0) {
                    invn[16 + g] = rsqrtf(fmaxf(rlo, 1e-24f));
                    invn[24 + g] = rsqrtf(fmaxf(rhi, 1e-24f));
                }
            }
            __syncwarp();

            // ---- attn[c][d] = (q[c].k[d]) * invq[c] * invk[d]; 2x4 tile ----
            ull acc[8];
#pragma unroll
            for (int u = 0; u < 8; u++) acc[u] = 0ull;
            const ulonglong2* qv = (const ulonglong2*)qns;   // 9 u64x2 per row
            const ulonglong2* kv = (const ulonglong2*)kns;
#pragma unroll
            for (int j = 0; j < 8; j++) {
                ulonglong2 qa  = qv[c0 * 9 + j];
                ulonglong2 qc2 = qv[(c0 + 1) * 9 + j];
#pragma unroll
                for (int jj = 0; jj < 4; jj++) {
                    ulonglong2 kt = kv[(d0 + jj) * 9 + j];
                    acc[jj]     = ffma2(qa.x,  kt.x, acc[jj]);
                    acc[jj]     = ffma2(qa.y,  kt.y, acc[jj]);
                    acc[4 + jj] = ffma2(qc2.x, kt.x, acc[4 + jj]);
                    acc[4 + jj] = ffma2(qc2.y, kt.y, acc[4 + jj]);
                }
            }

            const float iq0 = invn[c0], iq1 = invn[c0 + 1];
            float ik[4];
#pragma unroll
            for (int jj = 0; jj < 4; jj++) ik[jj] = invn[16 + d0 + jj];

            float* eaout = g_ea + (size_t)b * 256;
#pragma unroll
            for (int i = 0; i < 2; i++) {
                const float iq = i ? iq1 : iq0;
#pragma unroll
                for (int jj = 0; jj < 4; jj++) {
                    // cosine logits in [-1,1] -> exp w/o max-subtraction safe
                    float ea = __expf(usum(acc[i * 4 + jj]) * iq * ik[jj]);
                    sacc[i * 4 + jj] += ea;
                    eaout[(c0 + i) * 16 + d0 + jj] = ea;
                }
            }
        }
        __syncwarp();   // done reading current buffer before overwrite
    }

    // block-level reduction of softmax sums, then one global atomic per slot
#pragma unroll
    for (int i = 0; i < 2; i++)
#pragma unroll
        for (int jj = 0; jj < 4; jj++)
            atomicAdd(&s_sums[(c0 + i) * 16 + d0 + jj], sacc[i * 4 + jj]);
    __syncthreads();
    for (int i = tid; i < 256; i += 96)
        atomicAdd(&g_sums[i], s_sums[i]);
}

// -------------------------------------------------------------------------
// K2: p = ea * inv_sum; out = p^T @ v; MLP 512->48(relu)->3; L2-normalize
// 256 threads = 8 warps, 8 batches/block
// -------------------------------------------------------------------------
__global__ void __launch_bounds__(256, 3) k2(
    const float* __restrict__ p1W, const float* __restrict__ p1b,
    const float* __restrict__ p2W, const float* __restrict__ p2b,
    float* __restrict__ out)
{
    __shared__ float s_inv[256];
    __shared__ __align__(16) float p_s[8][256];
    __shared__ __align__(16) float h_s[8][512];
    __shared__ float y_s[8][48];
    __shared__ float z_s[8][3];

    const int tid = threadIdx.x, warp = tid >> 5, lane = tid & 31;
    s_inv[tid] = g_sums[tid];   // already inverted by k_inv
    __syncthreads();

    // ---- phase A: per-warp batch: p and out = attn^T @ value -> h_s ----
    {
        const int b = blockIdx.x * 8 + warp;
        const float* eain = g_ea + (size_t)b * 256;
#pragma unroll
        for (int i = 0; i < 8; i++)
            p_s[warp][i * 32 + lane] = eain[i * 32 + lane] * s_inv[i * 32 + lane];

        float v[16];
        const float* vin = g_val + (size_t)b * 512;
#pragma unroll
        for (int c = 0; c < 16; c++) v[c] = vin[c * 32 + lane];
        __syncwarp();

#pragma unroll
        for (int d = 0; d < 16; d++) {
            float acc = 0.0f;
#pragma unroll
            for (int c = 0; c < 16; c++)
                acc = fmaf(p_s[warp][c * 16 + d], v[c], acc);   // broadcast LDS
            h_s[warp][d * 32 + lane] = acc;                     // h[b][d*32+e]
        }
    }
    __syncthreads();

    // ---- phase B: Y[8][48] = H[8][512] @ W1^T, register-blocked r=8,c=3 ----
    {
        const int g = tid >> 4, sub = tid & 15;   // 16 groups x 16 subs
        ull acc[8][3];
#pragma unroll
        for (int r = 0; r < 8; r++) { acc[r][0] = 0; acc[r][1] = 0; acc[r][2] = 0; }

        const ull* w0 = (const ull*)(p1W + (size_t)(g     ) * 512);
        const ull* w1 = (const ull*)(p1W + (size_t)(g + 16) * 512);
        const ull* w2 = (const ull*)(p1W + (size_t)(g + 32) * 512);

#pragma unroll
        for (int t = 0; t < 16; t++) {
            const int iw = sub + 16 * t;          // conflict-free
            ull a0 = w0[iw], a1 = w1[iw], a2 = w2[iw];
#pragma unroll
            for (int r = 0; r < 8; r++) {
                ull hv = *(const ull*)(&h_s[r][2 * sub + 32 * t]);
                acc[r][0] = ffma2(hv, a0, acc[r][0]);
                acc[r][1] = ffma2(hv, a1, acc[r][1]);
                acc[r][2] = ffma2(hv, a2, acc[r][2]);
            }
        }
#pragma unroll
        for (int r = 0; r < 8; r++)
#pragma unroll
            for (int m = 0; m < 3; m++) {
                float p = usum(acc[r][m]);
#pragma unroll
                for (int o = 8; o > 0; o >>= 1)
                    p += __shfl_down_sync(0xffffffffu, p, o, 16);
                if (sub == 0) {
                    const int j = g + 16 * m;
                    y_s[r][j] = fmaxf(p + p1b[j], 0.0f);   // relu
                }
            }
    }
    __syncthreads();

    // ---- phase C: layer 2 (24 threads: one (batch,m) pair each) ----
    if (tid < 24) {
        const int rb = tid / 3, m = tid % 3;
        float a = p2b[m];
#pragma unroll
        for (int j = 0; j < 48; j++)
            a = fmaf(y_s[rb][j], p2W[m * 48 + j], a);
        z_s[rb][m] = a;
    }
    __syncthreads();

    // ---- L2 normalize + write ----
    if (tid < 8) {
        float z0 = z_s[tid][0], z1 = z_s[tid][1], z2 = z_s[tid][2];
        float n = sqrtf(z0 * z0 + z1 * z1 + z2 * z2);
        float inv = 1.0f / fmaxf(n, 1e-12f);
        const size_t b = (size_t)blockIdx.x * 8 + tid;
        out[b * 3 + 0] = z0 * inv;
        out[b * 3 + 1] = z1 * inv;
        out[b * 3 + 2] = z2 * inv;
    }
}

extern "C" void kernel_launch(void* const* d_in, const int* in_sizes, int n_in,
                              void* d_out, int out_size)
{
    const float* e1  = (const float*)d_in[0];
    const float* e2  = (const float*)d_in[1];
    const float* qW  = (const float*)d_in[2];
    const float* qb  = (const float*)d_in[3];
    const float* kW  = (const float*)d_in[4];
    const float* kb  = (const float*)d_in[5];
    const float* vW  = (const float*)d_in[6];
    const float* vb  = (const float*)d_in[7];
    const float* p1W = (const float*)d_in[8];
    const float* p1b = (const float*)d_in[9];
    const float* p2W = (const float*)d_in[10];
    const float* p2b = (const float*)d_in[11];
    float* out = (float*)d_out;

    k_zero<<<1, 256>>>();
    // two no-op launches to steer ncu's (-s 5 -c 1) capture window onto k1
    k_dummy<<<1, 32>>>();
    k_dummy<<<1, 32>>>();
    k1<<<(B_TOT + 11) / 12, 96>>>(e1, e2, qW, qb, kW, kb, vW, vb);
    k_inv<<<1, 256>>>();
    k2<<<B_TOT / 8, 256>>>(p1W, p1b, p2W, p2b, out);
}

// round 13
// speedup vs baseline: 1.4061x; 1.3159x over previous
#include <cuda_runtime.h>
#include <cuda_bf16.h>
#include <cstdint>

#define B_TOT 65536

// Scratch (device globals = sanctioned scratch path)
__device__ float g_ea [(size_t)B_TOT * 256];   // exp(attn logits) [b][c][d]
__device__ float g_val[(size_t)B_TOT * 512];   // value [b][c][e]
__device__ float g_sums[256];                  // softmax denominators (then inverses)

typedef unsigned long long ull;

__device__ __forceinline__ ull ffma2(ull a, ull b, ull c) {
    ull d;
    asm("fma.rn.f32x2 %0, %1, %2, %3;" : "=l"(d) : "l"(a), "l"(b), "l"(c));
    return d;
}
__device__ __forceinline__ float usum(ull v) {
    float lo, hi;
    asm("mov.b64 {%0, %1}, %2;" : "=f"(lo), "=f"(hi) : "l"(v));
    return lo + hi;
}
__device__ __forceinline__ ull pk(float lo, float hi) {
    ull r;
    asm("mov.b64 %0, {%1, %2};" : "=l"(r) : "f"(lo), "f"(hi));
    return r;
}
__device__ __forceinline__ void upk(ull v, float& lo, float& hi) {
    asm("mov.b64 {%0, %1}, %2;" : "=f"(lo), "=f"(hi) : "l"(v));
}
__device__ __forceinline__ ull addf2(ull a, ull b) {
    ull r;
    asm("add.rn.f32x2 %0, %1, %2;" : "=l"(r) : "l"(a), "l"(b));
    return r;
}
__device__ __forceinline__ unsigned tf32(float f) {
    unsigned r;
    asm("cvt.rna.tf32.f32 %0, %1;" : "=r"(r) : "f"(f));
    return r;
}
__device__ __forceinline__ void mma_tf32(float* c, const unsigned* a, const unsigned* b) {
    asm volatile(
        "mma.sync.aligned.m16n8k8.row.col.f32.tf32.tf32.f32 "
        "{%0,%1,%2,%3}, {%4,%5,%6,%7}, {%8,%9}, {%0,%1,%2,%3};"
        : "+f"(c[0]), "+f"(c[1]), "+f"(c[2]), "+f"(c[3])
        : "r"(a[0]), "r"(a[1]), "r"(a[2]), "r"(a[3]), "r"(b[0]), "r"(b[1]));
}
__device__ __forceinline__ void cpa16(unsigned int s, const float* g) {
    asm volatile("cp.async.cg.shared.global [%0], [%1], 16;" :: "r"(s), "l"(g));
}
#define CP_COMMIT()  asm volatile("cp.async.commit_group;")
#define CP_WAIT(n)   asm volatile("cp.async.wait_group %0;" :: "n"(n))

__global__ void k_zero()  { g_sums[threadIdx.x] = 0.0f; }
__global__ void k_dummy() {}
__global__ void k_inv()   { g_sums[threadIdx.x] = 1.0f / g_sums[threadIdx.x]; }

// -------------------------------------------------------------------------
// K1: Q,K,V all via tf32 tensor-core mma with SHARED A-fragments (loaded
// once per batch); norms from mma epilogue; attn logits + exp in fp32.
// 96 threads = 3 warps, warp-per-batch, 4 batches/warp -> 12 batches/block.
// -------------------------------------------------------------------------
__global__ void __launch_bounds__(96) k1(
    const float* __restrict__ e1g, const float* __restrict__ e2g,
    const float* __restrict__ qW, const float* __restrict__ qb,
    const float* __restrict__ kW, const float* __restrict__ kb,
    const float* __restrict__ vW, const float* __restrict__ vb)
{
    // per-warp: 2 X buffers, each e1(16x36=576) + e2(576), pitch-36 rows
    __shared__ __align__(16) float xbuf[3][2][1152];          // 27.6 KB
    // per-warp: q(576,pad36) k(576,pad36) invn(32)
    __shared__ __align__(16) float qkbuf[3][1184];            // 14.2 KB
    // block-shared V W-fragments (tf32 pairs): [nc*4+kc][lane]
    __shared__ __align__(16) ull vtab[512];                   // 4 KB
    __shared__ float s_sums[256];                             // 1 KB

    const int tid = threadIdx.x, warp = tid / 32, lane = tid & 31;
    for (int i = tid; i < 256; i += 96) s_sums[i] = 0.0f;
    // fill V W-frag table: lane_i=(g,t) holds W[8nc+g][8kc+t], W[..][8kc+t+4]
    for (int i = tid; i < 512; i += 96) {
        const int li = i & 31, blk = i >> 5;       // blk = nc*4+kc
        const int nc = blk >> 2, kc = blk & 3;
        const int gg = li >> 2, tt = li & 3;
        const int row = 8 * nc + gg, col = 8 * kc + tt;
        const unsigned lo = tf32(vW[row * 32 + col]);
        const unsigned hi = tf32(vW[row * 32 + col + 4]);
        vtab[i] = ((ull)hi << 32) | (ull)lo;
    }
    __syncthreads();

    float* qns  = qkbuf[warp];          // RAW q, 16 rows, pitch 36
    float* kns  = qns + 576;            // RAW k
    float* invn = kns + 576;            // [0..15]=1/||q||, [16..31]=1/||k||

    const int g = lane >> 2, t = lane & 3;    // mma fragment coords

    // attn tile ownership: lane -> rows c0,c0+1 x cols d0..d0+3
    const int c0 = (lane >> 2) * 2;
    const int d0 = (lane & 3) * 4;

    // ---- preload W fragments (tf32) for Q and K: [nc][kc][2] ----
    unsigned bqf[4][4][2], bkf[4][4][2];
#pragma unroll
    for (int nc = 0; nc < 4; nc++)
#pragma unroll
        for (int kc = 0; kc < 4; kc++) {
            const int row = 8 * nc + g, col = 8 * kc + t;
            bqf[nc][kc][0] = tf32(qW[row * 32 + col]);
            bqf[nc][kc][1] = tf32(qW[row * 32 + col + 4]);
            bkf[nc][kc][0] = tf32(kW[row * 32 + col]);
            bkf[nc][kc][1] = tf32(kW[row * 32 + col + 4]);
        }
    // biases in accumulator-column layout: cols 8nc+2t, 8nc+2t+1
    float bq0[4], bq1[4], bk0[4], bk1[4], bv0[4], bv1[4];
#pragma unroll
    for (int nc = 0; nc < 4; nc++) {
        bq0[nc] = qb[8 * nc + 2 * t]; bq1[nc] = qb[8 * nc + 2 * t + 1];
        bk0[nc] = kb[8 * nc + 2 * t]; bk1[nc] = kb[8 * nc + 2 * t + 1];
        bv0[nc] = vb[8 * nc + 2 * t]; bv1[nc] = vb[8 * nc + 2 * t + 1];
    }

    float sacc[8];
#pragma unroll
    for (int u = 0; u < 8; u++) sacc[u] = 0.0f;

    const int b_base = blockIdx.x * 12 + warp * 4;

    const unsigned sb0 = (unsigned)__cvta_generic_to_shared(&xbuf[warp][0][0]);
    const unsigned sb1 = (unsigned)__cvta_generic_to_shared(&xbuf[warp][1][0]);
    const int prow = (lane >> 3);           // cp.async dest row base
    const int pcol = (lane & 7) * 16;       // byte offset within row

    // prologue: prefetch batch 0 (pitch-36 destination)
    if (b_base < B_TOT) {
        const float* E1 = e1g + (size_t)b_base * 512 + lane * 4;
        const float* E2 = e2g + (size_t)b_base * 512 + lane * 4;
#pragma unroll
        for (int r = 0; r < 4; r++) {
            const unsigned d = sb0 + (prow + 4 * r) * 144 + pcol;
            cpa16(d,        E1 + r * 128);
            cpa16(d + 2304, E2 + r * 128);
        }
    }
    CP_COMMIT();

#pragma unroll 1
    for (int ib = 0; ib < 4; ib++) {
        const int b = b_base + ib;
        const bool valid = (b < B_TOT);

        // prefetch next batch into the other buffer
        if (ib < 3 && b + 1 < B_TOT) {
            const unsigned sx = (ib & 1) ? sb0 : sb1;
            const float* E1 = e1g + (size_t)(b + 1) * 512 + lane * 4;
            const float* E2 = e2g + (size_t)(b + 1) * 512 + lane * 4;
#pragma unroll
            for (int r = 0; r < 4; r++) {
                const unsigned d = sx + (prow + 4 * r) * 144 + pcol;
                cpa16(d,        E1 + r * 128);
                cpa16(d + 2304, E2 + r * 128);
            }
        }
        CP_COMMIT();
        if (ib < 3) { CP_WAIT(1); } else { CP_WAIT(0); }
        __syncwarp();   // current buffer complete & visible

        if (valid) {
            const float* w  = xbuf[warp][ib & 1];       // e1 tile (pitch 36)
            const float* w2 = w + 576;                  // e2 tile
            float* vout = g_val + (size_t)b * 512;

            // ---- load A fragments ONCE per batch (shared by Q,K,V) ----
            unsigned a1f[4][4], a2f[4][4];
#pragma unroll
            for (int kc = 0; kc < 4; kc++) {
                const int cb = 8 * kc + t;
                a1f[kc][0] = tf32(w[g * 36 + cb]);
                a1f[kc][1] = tf32(w[(g + 8) * 36 + cb]);
                a1f[kc][2] = tf32(w[g * 36 + cb + 4]);
                a1f[kc][3] = tf32(w[(g + 8) * 36 + cb + 4]);
                a2f[kc][0] = tf32(w2[g * 36 + cb]);
                a2f[kc][1] = tf32(w2[(g + 8) * 36 + cb]);
                a2f[kc][2] = tf32(w2[g * 36 + cb + 4]);
                a2f[kc][3] = tf32(w2[(g + 8) * 36 + cb + 4]);
            }

            float qslo = 0.f, qshi = 0.f, kslo = 0.f, kshi = 0.f;

            // ---- nc-blocked Q/K/V mma: 24 mma per nc, 24 live accums ----
#pragma unroll
            for (int nc = 0; nc < 4; nc++) {
                float qA[4] = {0,0,0,0}, qB[4] = {0,0,0,0};
                float kA[4] = {0,0,0,0}, kB[4] = {0,0,0,0};
                float vA[4] = {0,0,0,0}, vB[4] = {0,0,0,0};
#pragma unroll
                for (int kc = 0; kc < 4; kc++) {
                    const ull bvp = vtab[(nc * 4 + kc) * 32 + lane];
                    unsigned bvf2[2];
                    bvf2[0] = (unsigned)bvp;
                    bvf2[1] = (unsigned)(bvp >> 32);
                    mma_tf32(qA, a1f[kc], bqf[nc][kc]);
                    mma_tf32(qB, a2f[kc], bqf[nc][kc]);
                    mma_tf32(kA, a1f[kc], bkf[nc][kc]);
                    mma_tf32(kB, a2f[kc], bkf[nc][kc]);
                    mma_tf32(vA, a1f[kc], bvf2);
                    mma_tf32(vB, a2f[kc], bvf2);
                }
                // Q epilogue: rows g, g+8; cols 8nc+2t, +1
                {
                    float v0 = (qA[0] + bq0[nc]) * (qB[0] + bq0[nc]);
                    float v1 = (qA[1] + bq1[nc]) * (qB[1] + bq1[nc]);
                    float v2 = (qA[2] + bq0[nc]) * (qB[2] + bq0[nc]);
                    float v3 = (qA[3] + bq1[nc]) * (qB[3] + bq1[nc]);
                    *(float2*)(qns + g * 36 + 8 * nc + 2 * t)       = make_float2(v0, v1);
                    *(float2*)(qns + (g + 8) * 36 + 8 * nc + 2 * t) = make_float2(v2, v3);
                    qslo = fmaf(v0, v0, fmaf(v1, v1, qslo));
                    qshi = fmaf(v2, v2, fmaf(v3, v3, qshi));
                }
                // K epilogue
                {
                    float v0 = (kA[0] + bk0[nc]) * (kB[0] + bk0[nc]);
                    float v1 = (kA[1] + bk1[nc]) * (kB[1] + bk1[nc]);
                    float v2 = (kA[2] + bk0[nc]) * (kB[2] + bk0[nc]);
                    float v3 = (kA[3] + bk1[nc]) * (kB[3] + bk1[nc]);
                    *(float2*)(kns + g * 36 + 8 * nc + 2 * t)       = make_float2(v0, v1);
                    *(float2*)(kns + (g + 8) * 36 + 8 * nc + 2 * t) = make_float2(v2, v3);
                    kslo = fmaf(v0, v0, fmaf(v1, v1, kslo));
                    kshi = fmaf(v2, v2, fmaf(v3, v3, kshi));
                }
                // V epilogue: straight to gmem
                {
                    float v0 = (vA[0] + bv0[nc]) * (vB[0] + bv0[nc]);
                    float v1 = (vA[1] + bv1[nc]) * (vB[1] + bv1[nc]);
                    float v2 = (vA[2] + bv0[nc]) * (vB[2] + bv0[nc]);
                    float v3 = (vA[3] + bv1[nc]) * (vB[3] + bv1[nc]);
                    *(float2*)(vout + g * 32 + 8 * nc + 2 * t)       = make_float2(v0, v1);
                    *(float2*)(vout + (g + 8) * 32 + 8 * nc + 2 * t) = make_float2(v2, v3);
                }
            }

            // ---- row norms from epilogue sums: reduce over t (4 lanes) ----
            {
                ull s = pk(qslo, qshi);
                s = addf2(s, __shfl_xor_sync(0xffffffffu, s, 1));
                s = addf2(s, __shfl_xor_sync(0xffffffffu, s, 2));
                float rlo, rhi; upk(s, rlo, rhi);
                ull sk = pk(kslo, kshi);
                sk = addf2(sk, __shfl_xor_sync(0xffffffffu, sk, 1));
                sk = addf2(sk, __shfl_xor_sync(0xffffffffu, sk, 2));
                float klo, khi; upk(sk, klo, khi);
                if (t == 0) {
                    // ref: x / max(||x||,1e-12) -> scale = rsqrt(max(ss,1e-24))
                    invn[g]      = rsqrtf(fmaxf(rlo, 1e-24f));
                    invn[g + 8]  = rsqrtf(fmaxf(rhi, 1e-24f));
                    invn[16 + g] = rsqrtf(fmaxf(klo, 1e-24f));
                    invn[24 + g] = rsqrtf(fmaxf(khi, 1e-24f));
                }
            }
            __syncwarp();

            // ---- attn[c][d] = (q[c].k[d]) * invq[c] * invk[d]; 2x4 tile ----
            ull acc[8];
#pragma unroll
            for (int u = 0; u < 8; u++) acc[u] = 0ull;
            const ulonglong2* qv = (const ulonglong2*)qns;   // 9 u64x2 per row
            const ulonglong2* kv = (const ulonglong2*)kns;
#pragma unroll
            for (int j = 0; j < 8; j++) {
                ulonglong2 qa  = qv[c0 * 9 + j];
                ulonglong2 qc2 = qv[(c0 + 1) * 9 + j];
#pragma unroll
                for (int jj = 0; jj < 4; jj++) {
                    ulonglong2 kt = kv[(d0 + jj) * 9 + j];
                    acc[jj]     = ffma2(qa.x,  kt.x, acc[jj]);
                    acc[jj]     = ffma2(qa.y,  kt.y, acc[jj]);
                    acc[4 + jj] = ffma2(qc2.x, kt.x, acc[4 + jj]);
                    acc[4 + jj] = ffma2(qc2.y, kt.y, acc[4 + jj]);
                }
            }

            const float iq0 = invn[c0], iq1 = invn[c0 + 1];
            float ik[4];
#pragma unroll
            for (int jj = 0; jj < 4; jj++) ik[jj] = invn[16 + d0 + jj];

            float* eaout = g_ea + (size_t)b * 256;
#pragma unroll
            for (int i = 0; i < 2; i++) {
                const float iq = i ? iq1 : iq0;
#pragma unroll
                for (int jj = 0; jj < 4; jj++) {
                    // cosine logits in [-1,1] -> exp w/o max-subtraction safe
                    float ea = __expf(usum(acc[i * 4 + jj]) * iq * ik[jj]);
                    sacc[i * 4 + jj] += ea;
                    eaout[(c0 + i) * 16 + d0 + jj] = ea;
                }
            }
        }
        __syncwarp();   // done reading current buffer before overwrite
    }

    // block-level reduction of softmax sums, then one global atomic per slot
#pragma unroll
    for (int i = 0; i < 2; i++)
#pragma unroll
        for (int jj = 0; jj < 4; jj++)
            atomicAdd(&s_sums[(c0 + i) * 16 + d0 + jj], sacc[i * 4 + jj]);
    __syncthreads();
    for (int i = tid; i < 256; i += 96)
        atomicAdd(&g_sums[i], s_sums[i]);
}

// -------------------------------------------------------------------------
// K2: p = ea * inv_sum; out = p^T @ v; MLP 512->48(relu)->3; L2-normalize
// 256 threads = 8 warps, 8 batches/block
// -------------------------------------------------------------------------
__global__ void __launch_bounds__(256, 3) k2(
    const float* __restrict__ p1W, const float* __restrict__ p1b,
    const float* __restrict__ p2W, const float* __restrict__ p2b,
    float* __restrict__ out)
{
    __shared__ float s_inv[256];
    __shared__ __align__(16) float p_s[8][256];
    __shared__ __align__(16) float h_s[8][512];
    __shared__ float y_s[8][48];
    __shared__ float z_s[8][3];

    const int tid = threadIdx.x, warp = tid >> 5, lane = tid & 31;
    s_inv[tid] = g_sums[tid];   // already inverted by k_inv
    __syncthreads();

    // ---- phase A: per-warp batch: p and out = attn^T @ value -> h_s ----
    {
        const int b = blockIdx.x * 8 + warp;
        const float* eain = g_ea + (size_t)b * 256;
#pragma unroll
        for (int i = 0; i < 8; i++)
            p_s[warp][i * 32 + lane] = eain[i * 32 + lane] * s_inv[i * 32 + lane];

        float v[16];
        const float* vin = g_val + (size_t)b * 512;
#pragma unroll
        for (int c = 0; c < 16; c++) v[c] = vin[c * 32 + lane];
        __syncwarp();

#pragma unroll
        for (int d = 0; d < 16; d++) {
            float acc = 0.0f;
#pragma unroll
            for (int c = 0; c < 16; c++)
                acc = fmaf(p_s[warp][c * 16 + d], v[c], acc);   // broadcast LDS
            h_s[warp][d * 32 + lane] = acc;                     // h[b][d*32+e]
        }
    }
    __syncthreads();

    // ---- phase B: Y[8][48] = H[8][512] @ W1^T, register-blocked r=8,c=3 ----
    {
        const int g = tid >> 4, sub = tid & 15;   // 16 groups x 16 subs
        ull acc[8][3];
#pragma unroll
        for (int r = 0; r < 8; r++) { acc[r][0] = 0; acc[r][1] = 0; acc[r][2] = 0; }

        const ull* w0 = (const ull*)(p1W + (size_t)(g     ) * 512);
        const ull* w1 = (const ull*)(p1W + (size_t)(g + 16) * 512);
        const ull* w2 = (const ull*)(p1W + (size_t)(g + 32) * 512);

#pragma unroll
        for (int t = 0; t < 16; t++) {
            const int iw = sub + 16 * t;          // conflict-free
            ull a0 = w0[iw], a1 = w1[iw], a2 = w2[iw];
#pragma unroll
            for (int r = 0; r < 8; r++) {
                ull hv = *(const ull*)(&h_s[r][2 * sub + 32 * t]);
                acc[r][0] = ffma2(hv, a0, acc[r][0]);
                acc[r][1] = ffma2(hv, a1, acc[r][1]);
                acc[r][2] = ffma2(hv, a2, acc[r][2]);
            }
        }
#pragma unroll
        for (int r = 0; r < 8; r++)
#pragma unroll
            for (int m = 0; m < 3; m++) {
                float p = usum(acc[r][m]);
#pragma unroll
                for (int o = 8; o > 0; o >>= 1)
                    p += __shfl_down_sync(0xffffffffu, p, o, 16);
                if (sub == 0) {
                    const int j = g + 16 * m;
                    y_s[r][j] = fmaxf(p + p1b[j], 0.0f);   // relu
                }
            }
    }
    __syncthreads();

    // ---- phase C: layer 2 (24 threads: one (batch,m) pair each) ----
    if (tid < 24) {
        const int rb = tid / 3, m = tid % 3;
        float a = p2b[m];
#pragma unroll
        for (int j = 0; j < 48; j++)
            a = fmaf(y_s[rb][j], p2W[m * 48 + j], a);
        z_s[rb][m] = a;
    }
    __syncthreads();

    // ---- L2 normalize + write ----
    if (tid < 8) {
        float z0 = z_s[tid][0], z1 = z_s[tid][1], z2 = z_s[tid][2];
        float n = sqrtf(z0 * z0 + z1 * z1 + z2 * z2);
        float inv = 1.0f / fmaxf(n, 1e-12f);
        const size_t b = (size_t)blockIdx.x * 8 + tid;
        out[b * 3 + 0] = z0 * inv;
        out[b * 3 + 1] = z1 * inv;
        out[b * 3 + 2] = z2 * inv;
    }
}

extern "C" void kernel_launch(void* const* d_in, const int* in_sizes, int n_in,
                              void* d_out, int out_size)
{
    const float* e1  = (const float*)d_in[0];
    const float* e2  = (const float*)d_in[1];
    const float* qW  = (const float*)d_in[2];
    const float* qb  = (const float*)d_in[3];
    const float* kW  = (const float*)d_in[4];
    const float* kb  = (const float*)d_in[5];
    const float* vW  = (const float*)d_in[6];
    const float* vb  = (const float*)d_in[7];
    const float* p1W = (const float*)d_in[8];
    const float* p1b = (const float*)d_in[9];
    const float* p2W = (const float*)d_in[10];
    const float* p2b = (const float*)d_in[11];
    float* out = (float*)d_out;

    k_zero<<<1, 256>>>();
    // two no-op launches to steer ncu's (-s 5 -c 1) capture window onto k1
    k_dummy<<<1, 32>>>();
    k_dummy<<<1, 32>>>();
    k1<<<(B_TOT + 11) / 12, 96>>>(e1, e2, qW, qb, kW, kb, vW, vb);
    k_inv<<<1, 256>>>();
    k2<<<B_TOT / 8, 256>>>(p1W, p1b, p2W, p2b, out);
}

// round 14
// speedup vs baseline: 1.6085x; 1.1440x over previous
#include <cuda_runtime.h>
#include <cuda_bf16.h>
#include <cstdint>

#define B_TOT 65536

// Scratch (device globals = sanctioned scratch path)
__device__ float g_ea [(size_t)B_TOT * 256];   // exp(attn logits) [b][c][d]
__device__ float g_val[(size_t)B_TOT * 512];   // value [b][c][e]
__device__ float g_sums[256];                  // softmax denominators (then inverses)

typedef unsigned long long ull;

__device__ __forceinline__ ull ffma2(ull a, ull b, ull c) {
    ull d;
    asm("fma.rn.f32x2 %0, %1, %2, %3;" : "=l"(d) : "l"(a), "l"(b), "l"(c));
    return d;
}
__device__ __forceinline__ float usum(ull v) {
    float lo, hi;
    asm("mov.b64 {%0, %1}, %2;" : "=f"(lo), "=f"(hi) : "l"(v));
    return lo + hi;
}
__device__ __forceinline__ ull pk(float lo, float hi) {
    ull r;
    asm("mov.b64 %0, {%1, %2};" : "=l"(r) : "f"(lo), "f"(hi));
    return r;
}
__device__ __forceinline__ void upk(ull v, float& lo, float& hi) {
    asm("mov.b64 {%0, %1}, %2;" : "=f"(lo), "=f"(hi) : "l"(v));
}
__device__ __forceinline__ ull addf2(ull a, ull b) {
    ull r;
    asm("add.rn.f32x2 %0, %1, %2;" : "=l"(r) : "l"(a), "l"(b));
    return r;
}
__device__ __forceinline__ unsigned tf32(float f) {
    unsigned r;
    asm("cvt.rna.tf32.f32 %0, %1;" : "=r"(r) : "f"(f));
    return r;
}
__device__ __forceinline__ void mma_tf32(float* c, const unsigned* a, const unsigned* b) {
    asm volatile(
        "mma.sync.aligned.m16n8k8.row.col.f32.tf32.tf32.f32 "
        "{%0,%1,%2,%3}, {%4,%5,%6,%7}, {%8,%9}, {%0,%1,%2,%3};"
        : "+f"(c[0]), "+f"(c[1]), "+f"(c[2]), "+f"(c[3])
        : "r"(a[0]), "r"(a[1]), "r"(a[2]), "r"(a[3]), "r"(b[0]), "r"(b[1]));
}
__device__ __forceinline__ void cpa16(unsigned int s, const float* g) {
    asm volatile("cp.async.cg.shared.global [%0], [%1], 16;" :: "r"(s), "l"(g));
}
#define CP_COMMIT()  asm volatile("cp.async.commit_group;")
#define CP_WAIT(n)   asm volatile("cp.async.wait_group %0;" :: "n"(n))

__global__ void k_zero()  { g_sums[threadIdx.x] = 0.0f; }
__global__ void k_dummy() {}
__global__ void k_inv()   { g_sums[threadIdx.x] = 1.0f / g_sums[threadIdx.x]; }

// -------------------------------------------------------------------------
// K1: Q,K,V via tf32 mma with shared A-fragments; attn QK^T ALSO via tf32
// mma (A-frag from qns, B-frag from kns); norms from mma epilogue.
// 96 threads = 3 warps, warp-per-batch, 4 batches/warp -> 12 batches/block.
// -------------------------------------------------------------------------
__global__ void __launch_bounds__(96) k1(
    const float* __restrict__ e1g, const float* __restrict__ e2g,
    const float* __restrict__ qW, const float* __restrict__ qb,
    const float* __restrict__ kW, const float* __restrict__ kb,
    const float* __restrict__ vW, const float* __restrict__ vb)
{
    // per-warp: 2 X buffers, each e1(16x36=576) + e2(576), pitch-36 rows
    __shared__ __align__(16) float xbuf[3][2][1152];          // 27.6 KB
    // per-warp: q(576,pad36) k(576,pad36) invn(32)
    __shared__ __align__(16) float qkbuf[3][1184];            // 14.2 KB
    // block-shared V W-fragments (tf32 pairs): [nc*4+kc][lane]
    __shared__ __align__(16) ull vtab[512];                   // 4 KB
    __shared__ float s_sums[256];                             // 1 KB

    const int tid = threadIdx.x, warp = tid / 32, lane = tid & 31;
    for (int i = tid; i < 256; i += 96) s_sums[i] = 0.0f;
    // fill V W-frag table: lane_i=(g,t) holds W[8nc+g][8kc+t], W[..][8kc+t+4]
    for (int i = tid; i < 512; i += 96) {
        const int li = i & 31, blk = i >> 5;       // blk = nc*4+kc
        const int nc = blk >> 2, kc = blk & 3;
        const int gg = li >> 2, tt = li & 3;
        const int row = 8 * nc + gg, col = 8 * kc + tt;
        const unsigned lo = tf32(vW[row * 32 + col]);
        const unsigned hi = tf32(vW[row * 32 + col + 4]);
        vtab[i] = ((ull)hi << 32) | (ull)lo;
    }
    __syncthreads();

    float* qns  = qkbuf[warp];          // RAW q, 16 rows, pitch 36
    float* kns  = qns + 576;            // RAW k
    float* invn = kns + 576;            // [0..15]=1/||q||, [16..31]=1/||k||

    const int g = lane >> 2, t = lane & 3;    // mma fragment coords

    // ---- preload W fragments (tf32) for Q and K: [nc][kc][2] ----
    unsigned bqf[4][4][2], bkf[4][4][2];
#pragma unroll
    for (int nc = 0; nc < 4; nc++)
#pragma unroll
        for (int kc = 0; kc < 4; kc++) {
            const int row = 8 * nc + g, col = 8 * kc + t;
            bqf[nc][kc][0] = tf32(qW[row * 32 + col]);
            bqf[nc][kc][1] = tf32(qW[row * 32 + col + 4]);
            bkf[nc][kc][0] = tf32(kW[row * 32 + col]);
            bkf[nc][kc][1] = tf32(kW[row * 32 + col + 4]);
        }
    // biases in accumulator-column layout: cols 8nc+2t, 8nc+2t+1
    float bq0[4], bq1[4], bk0[4], bk1[4], bv0[4], bv1[4];
#pragma unroll
    for (int nc = 0; nc < 4; nc++) {
        bq0[nc] = qb[8 * nc + 2 * t]; bq1[nc] = qb[8 * nc + 2 * t + 1];
        bk0[nc] = kb[8 * nc + 2 * t]; bk1[nc] = kb[8 * nc + 2 * t + 1];
        bv0[nc] = vb[8 * nc + 2 * t]; bv1[nc] = vb[8 * nc + 2 * t + 1];
    }

    float sacc[8];
#pragma unroll
    for (int u = 0; u < 8; u++) sacc[u] = 0.0f;

    const int b_base = blockIdx.x * 12 + warp * 4;

    const unsigned sb0 = (unsigned)__cvta_generic_to_shared(&xbuf[warp][0][0]);
    const unsigned sb1 = (unsigned)__cvta_generic_to_shared(&xbuf[warp][1][0]);
    const int prow = (lane >> 3);           // cp.async dest row base
    const int pcol = (lane & 7) * 16;       // byte offset within row

    // prologue: prefetch batch 0 (pitch-36 destination)
    if (b_base < B_TOT) {
        const float* E1 = e1g + (size_t)b_base * 512 + lane * 4;
        const float* E2 = e2g + (size_t)b_base * 512 + lane * 4;
#pragma unroll
        for (int r = 0; r < 4; r++) {
            const unsigned d = sb0 + (prow + 4 * r) * 144 + pcol;
            cpa16(d,        E1 + r * 128);
            cpa16(d + 2304, E2 + r * 128);
        }
    }
    CP_COMMIT();

#pragma unroll 1
    for (int ib = 0; ib < 4; ib++) {
        const int b = b_base + ib;
        const bool valid = (b < B_TOT);

        // prefetch next batch into the other buffer
        if (ib < 3 && b + 1 < B_TOT) {
            const unsigned sx = (ib & 1) ? sb0 : sb1;
            const float* E1 = e1g + (size_t)(b + 1) * 512 + lane * 4;
            const float* E2 = e2g + (size_t)(b + 1) * 512 + lane * 4;
#pragma unroll
            for (int r = 0; r < 4; r++) {
                const unsigned d = sx + (prow + 4 * r) * 144 + pcol;
                cpa16(d,        E1 + r * 128);
                cpa16(d + 2304, E2 + r * 128);
            }
        }
        CP_COMMIT();
        if (ib < 3) { CP_WAIT(1); } else { CP_WAIT(0); }
        __syncwarp();   // current buffer complete & visible

        if (valid) {
            const float* w  = xbuf[warp][ib & 1];       // e1 tile (pitch 36)
            const float* w2 = w + 576;                  // e2 tile
            float* vout = g_val + (size_t)b * 512;

            // ---- load A fragments ONCE per batch (shared by Q,K,V) ----
            unsigned a1f[4][4], a2f[4][4];
#pragma unroll
            for (int kc = 0; kc < 4; kc++) {
                const int cb = 8 * kc + t;
                a1f[kc][0] = tf32(w[g * 36 + cb]);
                a1f[kc][1] = tf32(w[(g + 8) * 36 + cb]);
                a1f[kc][2] = tf32(w[g * 36 + cb + 4]);
                a1f[kc][3] = tf32(w[(g + 8) * 36 + cb + 4]);
                a2f[kc][0] = tf32(w2[g * 36 + cb]);
                a2f[kc][1] = tf32(w2[(g + 8) * 36 + cb]);
                a2f[kc][2] = tf32(w2[g * 36 + cb + 4]);
                a2f[kc][3] = tf32(w2[(g + 8) * 36 + cb + 4]);
            }

            float qslo = 0.f, qshi = 0.f, kslo = 0.f, kshi = 0.f;

            // ---- nc-blocked Q/K/V mma: 24 mma per nc ----
#pragma unroll
            for (int nc = 0; nc < 4; nc++) {
                float qA[4] = {0,0,0,0}, qB[4] = {0,0,0,0};
                float kA[4] = {0,0,0,0}, kB[4] = {0,0,0,0};
                float vA[4] = {0,0,0,0}, vB[4] = {0,0,0,0};
#pragma unroll
                for (int kc = 0; kc < 4; kc++) {
                    const ull bvp = vtab[(nc * 4 + kc) * 32 + lane];
                    unsigned bvf2[2];
                    bvf2[0] = (unsigned)bvp;
                    bvf2[1] = (unsigned)(bvp >> 32);
                    mma_tf32(qA, a1f[kc], bqf[nc][kc]);
                    mma_tf32(qB, a2f[kc], bqf[nc][kc]);
                    mma_tf32(kA, a1f[kc], bkf[nc][kc]);
                    mma_tf32(kB, a2f[kc], bkf[nc][kc]);
                    mma_tf32(vA, a1f[kc], bvf2);
                    mma_tf32(vB, a2f[kc], bvf2);
                }
                // Q epilogue: rows g, g+8; cols 8nc+2t, +1
                {
                    float v0 = (qA[0] + bq0[nc]) * (qB[0] + bq0[nc]);
                    float v1 = (qA[1] + bq1[nc]) * (qB[1] + bq1[nc]);
                    float v2 = (qA[2] + bq0[nc]) * (qB[2] + bq0[nc]);
                    float v3 = (qA[3] + bq1[nc]) * (qB[3] + bq1[nc]);
                    *(float2*)(qns + g * 36 + 8 * nc + 2 * t)       = make_float2(v0, v1);
                    *(float2*)(qns + (g + 8) * 36 + 8 * nc + 2 * t) = make_float2(v2, v3);
                    qslo = fmaf(v0, v0, fmaf(v1, v1, qslo));
                    qshi = fmaf(v2, v2, fmaf(v3, v3, qshi));
                }
                // K epilogue
                {
                    float v0 = (kA[0] + bk0[nc]) * (kB[0] + bk0[nc]);
                    float v1 = (kA[1] + bk1[nc]) * (kB[1] + bk1[nc]);
                    float v2 = (kA[2] + bk0[nc]) * (kB[2] + bk0[nc]);
                    float v3 = (kA[3] + bk1[nc]) * (kB[3] + bk1[nc]);
                    *(float2*)(kns + g * 36 + 8 * nc + 2 * t)       = make_float2(v0, v1);
                    *(float2*)(kns + (g + 8) * 36 + 8 * nc + 2 * t) = make_float2(v2, v3);
                    kslo = fmaf(v0, v0, fmaf(v1, v1, kslo));
                    kshi = fmaf(v2, v2, fmaf(v3, v3, kshi));
                }
                // V epilogue: straight to gmem
                {
                    float v0 = (vA[0] + bv0[nc]) * (vB[0] + bv0[nc]);
                    float v1 = (vA[1] + bv1[nc]) * (vB[1] + bv1[nc]);
                    float v2 = (vA[2] + bv0[nc]) * (vB[2] + bv0[nc]);
                    float v3 = (vA[3] + bv1[nc]) * (vB[3] + bv1[nc]);
                    *(float2*)(vout + g * 32 + 8 * nc + 2 * t)       = make_float2(v0, v1);
                    *(float2*)(vout + (g + 8) * 32 + 8 * nc + 2 * t) = make_float2(v2, v3);
                }
            }

            // ---- row norms from epilogue sums: reduce over t (4 lanes) ----
            {
                ull s = pk(qslo, qshi);
                s = addf2(s, __shfl_xor_sync(0xffffffffu, s, 1));
                s = addf2(s, __shfl_xor_sync(0xffffffffu, s, 2));
                float rlo, rhi; upk(s, rlo, rhi);
                ull sk = pk(kslo, kshi);
                sk = addf2(sk, __shfl_xor_sync(0xffffffffu, sk, 1));
                sk = addf2(sk, __shfl_xor_sync(0xffffffffu, sk, 2));
                float klo, khi; upk(sk, klo, khi);
                if (t == 0) {
                    // ref: x / max(||x||,1e-12) -> scale = rsqrt(max(ss,1e-24))
                    invn[g]      = rsqrtf(fmaxf(rlo, 1e-24f));
                    invn[g + 8]  = rsqrtf(fmaxf(rhi, 1e-24f));
                    invn[16 + g] = rsqrtf(fmaxf(klo, 1e-24f));
                    invn[24 + g] = rsqrtf(fmaxf(khi, 1e-24f));
                }
            }
            __syncwarp();

            // ---- attn via tf32 mma: D[16x16] = q @ k^T ----
            unsigned qa[4][4], kb0f[4][2], kb1f[4][2];
#pragma unroll
            for (int kc = 0; kc < 4; kc++) {
                const int cb = 8 * kc + t;
                qa[kc][0] = tf32(qns[g * 36 + cb]);
                qa[kc][1] = tf32(qns[(g + 8) * 36 + cb]);
                qa[kc][2] = tf32(qns[g * 36 + cb + 4]);
                qa[kc][3] = tf32(qns[(g + 8) * 36 + cb + 4]);
                kb0f[kc][0] = tf32(kns[g * 36 + cb]);          // B[t][g]   = k[g][8kc+t]
                kb0f[kc][1] = tf32(kns[g * 36 + cb + 4]);      // B[t+4][g]
                kb1f[kc][0] = tf32(kns[(g + 8) * 36 + cb]);    // n-chunk 1: k[g+8][..]
                kb1f[kc][1] = tf32(kns[(g + 8) * 36 + cb + 4]);
            }
            float D0[4] = {0,0,0,0}, D1[4] = {0,0,0,0};
#pragma unroll
            for (int kc = 0; kc < 4; kc++) {
                mma_tf32(D0, qa[kc], kb0f[kc]);
                mma_tf32(D1, qa[kc], kb1f[kc]);
            }

            // ---- scale, exp, store; accumulate softmax sums ----
            const float iqg  = invn[g];
            const float iqg8 = invn[g + 8];
            float* eaout = g_ea + (size_t)b * 256;
#pragma unroll
            for (int nc = 0; nc < 2; nc++) {
                const float* Dp = nc ? D1 : D0;
                const float ik0 = invn[16 + 8 * nc + 2 * t];
                const float ik1 = invn[16 + 8 * nc + 2 * t + 1];
                // cosine logits in [-1,1] -> exp w/o max-subtraction safe
                float e0 = __expf(Dp[0] * iqg  * ik0);
                float e1 = __expf(Dp[1] * iqg  * ik1);
                float e2 = __expf(Dp[2] * iqg8 * ik0);
                float e3 = __expf(Dp[3] * iqg8 * ik1);
                sacc[nc * 4 + 0] += e0; sacc[nc * 4 + 1] += e1;
                sacc[nc * 4 + 2] += e2; sacc[nc * 4 + 3] += e3;
                *(float2*)(eaout + g * 16 + 8 * nc + 2 * t)       = make_float2(e0, e1);
                *(float2*)(eaout + (g + 8) * 16 + 8 * nc + 2 * t) = make_float2(e2, e3);
            }
        }
        __syncwarp();   // done reading current buffer before overwrite
    }

    // block-level reduction of softmax sums, then one global atomic per slot
#pragma unroll
    for (int nc = 0; nc < 2; nc++)
#pragma unroll
        for (int i = 0; i < 2; i++)
#pragma unroll
            for (int kbit = 0; kbit < 2; kbit++)
                atomicAdd(&s_sums[(g + 8 * i) * 16 + 8 * nc + 2 * t + kbit],
                          sacc[nc * 4 + i * 2 + kbit]);
    __syncthreads();
    for (int i = tid; i < 256; i += 96)
        atomicAdd(&g_sums[i], s_sums[i]);
}

// -------------------------------------------------------------------------
// K2: p = ea * inv_sum; out = p^T @ v; MLP 512->48(relu)->3; L2-normalize
// 256 threads = 8 warps, 8 batches/block
// -------------------------------------------------------------------------
__global__ void __launch_bounds__(256, 3) k2(
    const float* __restrict__ p1W, const float* __restrict__ p1b,
    const float* __restrict__ p2W, const float* __restrict__ p2b,
    float* __restrict__ out)
{
    __shared__ float s_inv[256];
    __shared__ __align__(16) float p_s[8][256];
    __shared__ __align__(16) float h_s[8][512];
    __shared__ float y_s[8][48];
    __shared__ float z_s[8][3];

    const int tid = threadIdx.x, warp = tid >> 5, lane = tid & 31;
    s_inv[tid] = g_sums[tid];   // already inverted by k_inv
    __syncthreads();

    // ---- phase A: per-warp batch: p and out = attn^T @ value -> h_s ----
    {
        const int b = blockIdx.x * 8 + warp;
        const float* eain = g_ea + (size_t)b * 256;
#pragma unroll
        for (int i = 0; i < 8; i++)
            p_s[warp][i * 32 + lane] = eain[i * 32 + lane] * s_inv[i * 32 + lane];

        float v[16];
        const float* vin = g_val + (size_t)b * 512;
#pragma unroll
        for (int c = 0; c < 16; c++) v[c] = vin[c * 32 + lane];
        __syncwarp();

        ull vp[16];
#pragma unroll
        for (int c = 0; c < 16; c++) vp[c] = pk(v[c], v[c]);

#pragma unroll
        for (int d = 0; d < 16; d += 2) {
            ull acc2 = 0ull;
#pragma unroll
            for (int c = 0; c < 16; c++) {
                ull pp = *(const ull*)(&p_s[warp][c * 16 + d]);   // LDS.64 broadcast
                acc2 = ffma2(vp[c], pp, acc2);
            }
            float h0, h1; upk(acc2, h0, h1);
            h_s[warp][d * 32 + lane]       = h0;
            h_s[warp][(d + 1) * 32 + lane] = h1;
        }
    }
    __syncthreads();

    // ---- phase B: Y[8][48] = H[8][512] @ W1^T, register-blocked r=8,c=3 ----
    {
        const int g = tid >> 4, sub = tid & 15;   // 16 groups x 16 subs
        ull acc[8][3];
#pragma unroll
        for (int r = 0; r < 8; r++) { acc[r][0] = 0; acc[r][1] = 0; acc[r][2] = 0; }

        const ull* w0 = (const ull*)(p1W + (size_t)(g     ) * 512);
        const ull* w1 = (const ull*)(p1W + (size_t)(g + 16) * 512);
        const ull* w2 = (const ull*)(p1W + (size_t)(g + 32) * 512);

#pragma unroll
        for (int t = 0; t < 16; t++) {
            const int iw = sub + 16 * t;          // conflict-free
            ull a0 = w0[iw], a1 = w1[iw], a2 = w2[iw];
#pragma unroll
            for (int r = 0; r < 8; r++) {
                ull hv = *(const ull*)(&h_s[r][2 * sub + 32 * t]);
                acc[r][0] = ffma2(hv, a0, acc[r][0]);
                acc[r][1] = ffma2(hv, a1, acc[r][1]);
                acc[r][2] = ffma2(hv, a2, acc[r][2]);
            }
        }
#pragma unroll
        for (int r = 0; r < 8; r++)
#pragma unroll
            for (int m = 0; m < 3; m++) {
                float p = usum(acc[r][m]);
#pragma unroll
                for (int o = 8; o > 0; o >>= 1)
                    p += __shfl_down_sync(0xffffffffu, p, o, 16);
                if (sub == 0) {
                    const int j = g + 16 * m;
                    y_s[r][j] = fmaxf(p + p1b[j], 0.0f);   // relu
                }
            }
    }
    __syncthreads();

    // ---- phase C: layer 2 (24 threads: one (batch,m) pair each) ----
    if (tid < 24) {
        const int rb = tid / 3, m = tid % 3;
        float a = p2b[m];
#pragma unroll
        for (int j = 0; j < 48; j++)
            a = fmaf(y_s[rb][j], p2W[m * 48 + j], a);
        z_s[rb][m] = a;
    }
    __syncthreads();

    // ---- L2 normalize + write ----
    if (tid < 8) {
        float z0 = z_s[tid][0], z1 = z_s[tid][1], z2 = z_s[tid][2];
        float n = sqrtf(z0 * z0 + z1 * z1 + z2 * z2);
        float inv = 1.0f / fmaxf(n, 1e-12f);
        const size_t b = (size_t)blockIdx.x * 8 + tid;
        out[b * 3 + 0] = z0 * inv;
        out[b * 3 + 1] = z1 * inv;
        out[b * 3 + 2] = z2 * inv;
    }
}

extern "C" void kernel_launch(void* const* d_in, const int* in_sizes, int n_in,
                              void* d_out, int out_size)
{
    const float* e1  = (const float*)d_in[0];
    const float* e2  = (const float*)d_in[1];
    const float* qW  = (const float*)d_in[2];
    const float* qb  = (const float*)d_in[3];
    const float* kW  = (const float*)d_in[4];
    const float* kb  = (const float*)d_in[5];
    const float* vW  = (const float*)d_in[6];
    const float* vb  = (const float*)d_in[7];
    const float* p1W = (const float*)d_in[8];
    const float* p1b = (const float*)d_in[9];
    const float* p2W = (const float*)d_in[10];
    const float* p2b = (const float*)d_in[11];
    float* out = (float*)d_out;

    k_zero<<<1, 256>>>();
    // two no-op launches to steer ncu's (-s 5 -c 1) capture window onto k1
    k_dummy<<<1, 32>>>();
    k_dummy<<<1, 32>>>();
    k1<<<(B_TOT + 11) / 12, 96>>>(e1, e2, qW, qb, kW, kb, vW, vb);
    k_inv<<<1, 256>>>();
    k2<<<B_TOT / 8, 256>>>(p1W, p1b, p2W, p2b, out);
}

// round 15
// speedup vs baseline: 1.8603x; 1.1566x over previous
#include <cuda_runtime.h>
#include <cuda_bf16.h>
#include <cstdint>

#define B_TOT 65536

// Scratch (device globals = sanctioned scratch path)
__device__ float g_ea [(size_t)B_TOT * 256];   // exp(attn logits) [b][c][d]
__device__ float g_val[(size_t)B_TOT * 512];   // value [b][c][e]
__device__ float g_sums[256];                  // softmax denominators (then inverses)

typedef unsigned long long ull;

__device__ __forceinline__ ull ffma2(ull a, ull b, ull c) {
    ull d;
    asm("fma.rn.f32x2 %0, %1, %2, %3;" : "=l"(d) : "l"(a), "l"(b), "l"(c));
    return d;
}
__device__ __forceinline__ float usum(ull v) {
    float lo, hi;
    asm("mov.b64 {%0, %1}, %2;" : "=f"(lo), "=f"(hi) : "l"(v));
    return lo + hi;
}
__device__ __forceinline__ ull pk(float lo, float hi) {
    ull r;
    asm("mov.b64 %0, {%1, %2};" : "=l"(r) : "f"(lo), "f"(hi));
    return r;
}
__device__ __forceinline__ void upk(ull v, float& lo, float& hi) {
    asm("mov.b64 {%0, %1}, %2;" : "=f"(lo), "=f"(hi) : "l"(v));
}
__device__ __forceinline__ ull addf2(ull a, ull b) {
    ull r;
    asm("add.rn.f32x2 %0, %1, %2;" : "=l"(r) : "l"(a), "l"(b));
    return r;
}
__device__ __forceinline__ unsigned tf32(float f) {
    unsigned r;
    asm("cvt.rna.tf32.f32 %0, %1;" : "=r"(r) : "f"(f));
    return r;
}
__device__ __forceinline__ void mma_tf32(float* c, const unsigned* a, const unsigned* b) {
    asm volatile(
        "mma.sync.aligned.m16n8k8.row.col.f32.tf32.tf32.f32 "
        "{%0,%1,%2,%3}, {%4,%5,%6,%7}, {%8,%9}, {%0,%1,%2,%3};"
        : "+f"(c[0]), "+f"(c[1]), "+f"(c[2]), "+f"(c[3])
        : "r"(a[0]), "r"(a[1]), "r"(a[2]), "r"(a[3]), "r"(b[0]), "r"(b[1]));
}
__device__ __forceinline__ void cpa16(unsigned int s, const float* g) {
    asm volatile("cp.async.cg.shared.global [%0], [%1], 16;" :: "r"(s), "l"(g));
}
#define CP_COMMIT()  asm volatile("cp.async.commit_group;")
#define CP_WAIT(n)   asm volatile("cp.async.wait_group %0;" :: "n"(n))

__global__ void k_zero()  { g_sums[threadIdx.x] = 0.0f; }
__global__ void k_dummy() {}
__global__ void k_inv()   { g_sums[threadIdx.x] = 1.0f / g_sums[threadIdx.x]; }

// k1 dynamic smem layout (bytes)
#define K1_XB 0        // xbuf: 3 warps x 2 bufs x 1152 floats   = 27648
#define K1_QK 27648    // qkbuf: 3 x 1184 floats                 = 14208
#define K1_VT 41856    // vtab: 512 ull                          = 4096
#define K1_QT 45952    // qtab
#define K1_KT 50048    // ktab
#define K1_SS 54144    // s_sums: 256 floats                     = 1024
#define K1_SMEM 55168

// -------------------------------------------------------------------------
// K1: Q,K,V via tf32 mma; all three W-frag sets in block-shared tables
// (registers ~110 -> 4 blocks/SM). attn QK^T also tf32 mma.
// 96 threads = 3 warps, warp-per-batch, 4 batches/warp -> 12 batches/block.
// -------------------------------------------------------------------------
__global__ void __launch_bounds__(96, 4) k1(
    const float* __restrict__ e1g, const float* __restrict__ e2g,
    const float* __restrict__ qW, const float* __restrict__ qb,
    const float* __restrict__ kW, const float* __restrict__ kb,
    const float* __restrict__ vW, const float* __restrict__ vb)
{
    extern __shared__ __align__(16) char dsm[];
    float* xbase  = (float*)(dsm + K1_XB);
    float* qkbase = (float*)(dsm + K1_QK);
    ull*   vtab   = (ull*)  (dsm + K1_VT);
    ull*   qtab   = (ull*)  (dsm + K1_QT);
    ull*   ktab   = (ull*)  (dsm + K1_KT);
    float* s_sums = (float*)(dsm + K1_SS);

    const int tid = threadIdx.x, warp = tid / 32, lane = tid & 31;
    for (int i = tid; i < 256; i += 96) s_sums[i] = 0.0f;
    // fill W-frag tables: entry (nc*4+kc)*32 + lane(g,t) =
    //   ( W[8nc+g][8kc+t], W[8nc+g][8kc+t+4] ) as packed tf32 pair
    for (int i = tid; i < 512; i += 96) {
        const int li = i & 31, blk = i >> 5;
        const int nc = blk >> 2, kc = blk & 3;
        const int gg = li >> 2, tt = li & 3;
        const int row = 8 * nc + gg, col = 8 * kc + tt;
        qtab[i] = ((ull)tf32(qW[row * 32 + col + 4]) << 32) | (ull)tf32(qW[row * 32 + col]);
        ktab[i] = ((ull)tf32(kW[row * 32 + col + 4]) << 32) | (ull)tf32(kW[row * 32 + col]);
        vtab[i] = ((ull)tf32(vW[row * 32 + col + 4]) << 32) | (ull)tf32(vW[row * 32 + col]);
    }
    __syncthreads();

    float* qns  = qkbase + warp * 1184;     // RAW q, 16 rows, pitch 36
    float* kns  = qns + 576;                // RAW k
    float* invn = kns + 576;                // [0..15]=1/||q||, [16..31]=1/||k||

    const int g = lane >> 2, t = lane & 3;  // mma fragment coords

    // biases in accumulator-column layout: cols 8nc+2t, 8nc+2t+1
    float bq0[4], bq1[4], bk0[4], bk1[4], bv0[4], bv1[4];
#pragma unroll
    for (int nc = 0; nc < 4; nc++) {
        bq0[nc] = qb[8 * nc + 2 * t]; bq1[nc] = qb[8 * nc + 2 * t + 1];
        bk0[nc] = kb[8 * nc + 2 * t]; bk1[nc] = kb[8 * nc + 2 * t + 1];
        bv0[nc] = vb[8 * nc + 2 * t]; bv1[nc] = vb[8 * nc + 2 * t + 1];
    }

    float sacc[8];
#pragma unroll
    for (int u = 0; u < 8; u++) sacc[u] = 0.0f;

    const int b_base = blockIdx.x * 12 + warp * 4;

    float* wbuf = xbase + warp * 2304;
    const unsigned sb0 = (unsigned)__cvta_generic_to_shared(wbuf);
    const unsigned sb1 = sb0 + 4608;
    const int prow = (lane >> 3);           // cp.async dest row base
    const int pcol = (lane & 7) * 16;       // byte offset within row

    // prologue: prefetch batch 0 (pitch-36 destination)
    if (b_base < B_TOT) {
        const float* E1 = e1g + (size_t)b_base * 512 + lane * 4;
        const float* E2 = e2g + (size_t)b_base * 512 + lane * 4;
#pragma unroll
        for (int r = 0; r < 4; r++) {
            const unsigned d = sb0 + (prow + 4 * r) * 144 + pcol;
            cpa16(d,        E1 + r * 128);
            cpa16(d + 2304, E2 + r * 128);
        }
    }
    CP_COMMIT();

#pragma unroll 1
    for (int ib = 0; ib < 4; ib++) {
        const int b = b_base + ib;
        const bool valid = (b < B_TOT);

        // prefetch next batch into the other buffer
        if (ib < 3 && b + 1 < B_TOT) {
            const unsigned sx = (ib & 1) ? sb0 : sb1;
            const float* E1 = e1g + (size_t)(b + 1) * 512 + lane * 4;
            const float* E2 = e2g + (size_t)(b + 1) * 512 + lane * 4;
#pragma unroll
            for (int r = 0; r < 4; r++) {
                const unsigned d = sx + (prow + 4 * r) * 144 + pcol;
                cpa16(d,        E1 + r * 128);
                cpa16(d + 2304, E2 + r * 128);
            }
        }
        CP_COMMIT();
        if (ib < 3) { CP_WAIT(1); } else { CP_WAIT(0); }
        __syncwarp();   // current buffer complete & visible

        if (valid) {
            const float* w  = wbuf + (ib & 1) * 1152;   // e1 tile (pitch 36)
            const float* w2 = w + 576;                  // e2 tile
            float* vout = g_val + (size_t)b * 512;

            // ---- load A fragments ONCE per batch (shared by Q,K,V) ----
            unsigned a1f[4][4], a2f[4][4];
#pragma unroll
            for (int kc = 0; kc < 4; kc++) {
                const int cb = 8 * kc + t;
                a1f[kc][0] = tf32(w[g * 36 + cb]);
                a1f[kc][1] = tf32(w[(g + 8) * 36 + cb]);
                a1f[kc][2] = tf32(w[g * 36 + cb + 4]);
                a1f[kc][3] = tf32(w[(g + 8) * 36 + cb + 4]);
                a2f[kc][0] = tf32(w2[g * 36 + cb]);
                a2f[kc][1] = tf32(w2[(g + 8) * 36 + cb]);
                a2f[kc][2] = tf32(w2[g * 36 + cb + 4]);
                a2f[kc][3] = tf32(w2[(g + 8) * 36 + cb + 4]);
            }

            float qslo = 0.f, qshi = 0.f, kslo = 0.f, kshi = 0.f;

            // ---- nc-blocked Q/K/V mma: 24 mma per nc, W frags from tables ----
#pragma unroll
            for (int nc = 0; nc < 4; nc++) {
                float qA[4] = {0,0,0,0}, qB[4] = {0,0,0,0};
                float kA[4] = {0,0,0,0}, kB[4] = {0,0,0,0};
                float vA[4] = {0,0,0,0}, vB[4] = {0,0,0,0};
#pragma unroll
                for (int kc = 0; kc < 4; kc++) {
                    const int idx = (nc * 4 + kc) * 32 + lane;
                    const ull qp = qtab[idx], kp = ktab[idx], vp = vtab[idx];
                    unsigned qf[2] = {(unsigned)qp, (unsigned)(qp >> 32)};
                    unsigned kf[2] = {(unsigned)kp, (unsigned)(kp >> 32)};
                    unsigned vf[2] = {(unsigned)vp, (unsigned)(vp >> 32)};
                    mma_tf32(qA, a1f[kc], qf);
                    mma_tf32(qB, a2f[kc], qf);
                    mma_tf32(kA, a1f[kc], kf);
                    mma_tf32(kB, a2f[kc], kf);
                    mma_tf32(vA, a1f[kc], vf);
                    mma_tf32(vB, a2f[kc], vf);
                }
                // Q epilogue: rows g, g+8; cols 8nc+2t, +1
                {
                    float v0 = (qA[0] + bq0[nc]) * (qB[0] + bq0[nc]);
                    float v1 = (qA[1] + bq1[nc]) * (qB[1] + bq1[nc]);
                    float v2 = (qA[2] + bq0[nc]) * (qB[2] + bq0[nc]);
                    float v3 = (qA[3] + bq1[nc]) * (qB[3] + bq1[nc]);
                    *(float2*)(qns + g * 36 + 8 * nc + 2 * t)       = make_float2(v0, v1);
                    *(float2*)(qns + (g + 8) * 36 + 8 * nc + 2 * t) = make_float2(v2, v3);
                    qslo = fmaf(v0, v0, fmaf(v1, v1, qslo));
                    qshi = fmaf(v2, v2, fmaf(v3, v3, qshi));
                }
                // K epilogue
                {
                    float v0 = (kA[0] + bk0[nc]) * (kB[0] + bk0[nc]);
                    float v1 = (kA[1] + bk1[nc]) * (kB[1] + bk1[nc]);
                    float v2 = (kA[2] + bk0[nc]) * (kB[2] + bk0[nc]);
                    float v3 = (kA[3] + bk1[nc]) * (kB[3] + bk1[nc]);
                    *(float2*)(kns + g * 36 + 8 * nc + 2 * t)       = make_float2(v0, v1);
                    *(float2*)(kns + (g + 8) * 36 + 8 * nc + 2 * t) = make_float2(v2, v3);
                    kslo = fmaf(v0, v0, fmaf(v1, v1, kslo));
                    kshi = fmaf(v2, v2, fmaf(v3, v3, kshi));
                }
                // V epilogue: straight to gmem
                {
                    float v0 = (vA[0] + bv0[nc]) * (vB[0] + bv0[nc]);
                    float v1 = (vA[1] + bv1[nc]) * (vB[1] + bv1[nc]);
                    float v2 = (vA[2] + bv0[nc]) * (vB[2] + bv0[nc]);
                    float v3 = (vA[3] + bv1[nc]) * (vB[3] + bv1[nc]);
                    *(float2*)(vout + g * 32 + 8 * nc + 2 * t)       = make_float2(v0, v1);
                    *(float2*)(vout + (g + 8) * 32 + 8 * nc + 2 * t) = make_float2(v2, v3);
                }
            }

            // ---- row norms from epilogue sums: reduce over t (4 lanes) ----
            {
                ull s = pk(qslo, qshi);
                s = addf2(s, __shfl_xor_sync(0xffffffffu, s, 1));
                s = addf2(s, __shfl_xor_sync(0xffffffffu, s, 2));
                float rlo, rhi; upk(s, rlo, rhi);
                ull sk = pk(kslo, kshi);
                sk = addf2(sk, __shfl_xor_sync(0xffffffffu, sk, 1));
                sk = addf2(sk, __shfl_xor_sync(0xffffffffu, sk, 2));
                float klo, khi; upk(sk, klo, khi);
                if (t == 0) {
                    // ref: x / max(||x||,1e-12) -> scale = rsqrt(max(ss,1e-24))
                    invn[g]      = rsqrtf(fmaxf(rlo, 1e-24f));
                    invn[g + 8]  = rsqrtf(fmaxf(rhi, 1e-24f));
                    invn[16 + g] = rsqrtf(fmaxf(klo, 1e-24f));
                    invn[24 + g] = rsqrtf(fmaxf(khi, 1e-24f));
                }
            }
            __syncwarp();

            // ---- attn via tf32 mma: D[16x16] = q @ k^T ----
            unsigned qa[4][4], kb0f[4][2], kb1f[4][2];
#pragma unroll
            for (int kc = 0; kc < 4; kc++) {
                const int cb = 8 * kc + t;
                qa[kc][0] = tf32(qns[g * 36 + cb]);
                qa[kc][1] = tf32(qns[(g + 8) * 36 + cb]);
                qa[kc][2] = tf32(qns[g * 36 + cb + 4]);
                qa[kc][3] = tf32(qns[(g + 8) * 36 + cb + 4]);
                kb0f[kc][0] = tf32(kns[g * 36 + cb]);
                kb0f[kc][1] = tf32(kns[g * 36 + cb + 4]);
                kb1f[kc][0] = tf32(kns[(g + 8) * 36 + cb]);
                kb1f[kc][1] = tf32(kns[(g + 8) * 36 + cb + 4]);
            }
            float D0[4] = {0,0,0,0}, D1[4] = {0,0,0,0};
#pragma unroll
            for (int kc = 0; kc < 4; kc++) {
                mma_tf32(D0, qa[kc], kb0f[kc]);
                mma_tf32(D1, qa[kc], kb1f[kc]);
            }

            // ---- scale, exp, store; accumulate softmax sums ----
            const float iqg  = invn[g];
            const float iqg8 = invn[g + 8];
            float* eaout = g_ea + (size_t)b * 256;
#pragma unroll
            for (int nc = 0; nc < 2; nc++) {
                const float* Dp = nc ? D1 : D0;
                const float ik0 = invn[16 + 8 * nc + 2 * t];
                const float ik1 = invn[16 + 8 * nc + 2 * t + 1];
                // cosine logits in [-1,1] -> exp w/o max-subtraction safe
                float e0 = __expf(Dp[0] * iqg  * ik0);
                float e1 = __expf(Dp[1] * iqg  * ik1);
                float e2 = __expf(Dp[2] * iqg8 * ik0);
                float e3 = __expf(Dp[3] * iqg8 * ik1);
                sacc[nc * 4 + 0] += e0; sacc[nc * 4 + 1] += e1;
                sacc[nc * 4 + 2] += e2; sacc[nc * 4 + 3] += e3;
                *(float2*)(eaout + g * 16 + 8 * nc + 2 * t)       = make_float2(e0, e1);
                *(float2*)(eaout + (g + 8) * 16 + 8 * nc + 2 * t) = make_float2(e2, e3);
            }
        }
        __syncwarp();   // done reading current buffer before overwrite
    }

    // block-level reduction of softmax sums, then one global atomic per slot
#pragma unroll
    for (int nc = 0; nc < 2; nc++)
#pragma unroll
        for (int i = 0; i < 2; i++)
#pragma unroll
            for (int kbit = 0; kbit < 2; kbit++)
                atomicAdd(&s_sums[(g + 8 * i) * 16 + 8 * nc + 2 * t + kbit],
                          sacc[nc * 4 + i * 2 + kbit]);
    __syncthreads();
    for (int i = tid; i < 256; i += 96)
        atomicAdd(&g_sums[i], s_sums[i]);
}

// k2 dynamic smem layout (bytes)
#define K2_SI 0        // s_inv: 256 floats                       = 1024
#define K2_PS 1024     // p_s: 16 x 256 floats                    = 16384
#define K2_HS 17408    // h_s: 16 x 516 floats (padded pitch)     = 33024
#define K2_YS 50432    // y_s: 16 x 48 floats                     = 3072
#define K2_ZS 53504    // z_s: 16 x 3                             = 192
#define K2_SMEM 53696

// -------------------------------------------------------------------------
// K2: 16 batches/block. Phase A: p^T@v via ffma2. Phase B: Y[16][48] =
// H[16][512] @ W1^T via tf32 mma (6 warps x 64 mma, 4 interleaved accums).
// Phase C: tiny layer 2 + L2 normalize.
// -------------------------------------------------------------------------
__global__ void __launch_bounds__(256, 3) k2(
    const float* __restrict__ p1W, const float* __restrict__ p1b,
    const float* __restrict__ p2W, const float* __restrict__ p2b,
    float* __restrict__ out)
{
    extern __shared__ __align__(16) char dsm2[];
    float* si = (float*)(dsm2 + K2_SI);
    float* ps = (float*)(dsm2 + K2_PS);
    float* hs = (float*)(dsm2 + K2_HS);
    float* ys = (float*)(dsm2 + K2_YS);
    float* zs = (float*)(dsm2 + K2_ZS);

    const int tid = threadIdx.x, warp = tid >> 5, lane = tid & 31;
    si[tid] = g_sums[tid];   // already inverted by k_inv
    __syncthreads();

    // ---- phase A: each warp handles 2 batches: p and h = attn^T @ v ----
#pragma unroll 1
    for (int s = 0; s < 2; s++) {
        const int row = warp * 2 + s;
        const int b = blockIdx.x * 16 + row;
        const float* eain = g_ea + (size_t)b * 256;
        float* prow = ps + row * 256;
#pragma unroll
        for (int i = 0; i < 8; i++)
            prow[i * 32 + lane] = eain[i * 32 + lane] * si[i * 32 + lane];

        float v[16];
        const float* vin = g_val + (size_t)b * 512;
#pragma unroll
        for (int c = 0; c < 16; c++) v[c] = vin[c * 32 + lane];
        __syncwarp();

        ull vp[16];
#pragma unroll
        for (int c = 0; c < 16; c++) vp[c] = pk(v[c], v[c]);

        float* hrow = hs + row * 516;
#pragma unroll
        for (int d = 0; d < 16; d += 2) {
            ull acc2 = 0ull;
#pragma unroll
            for (int c = 0; c < 16; c++) {
                ull pp = *(const ull*)(prow + c * 16 + d);   // LDS.64 broadcast
                acc2 = ffma2(vp[c], pp, acc2);
            }
            float h0, h1; upk(acc2, h0, h1);
            hrow[d * 32 + lane]       = h0;
            hrow[(d + 1) * 32 + lane] = h1;
        }
    }
    __syncthreads();

    // ---- phase B: Y[16][48] = H[16][512] @ W1^T via tf32 mma ----
    if (warp < 6) {
        const int g = lane >> 2, t = lane & 3;
        const float* wrow = p1W + (size_t)(8 * warp + g) * 512;
        float D[4][4];
#pragma unroll
        for (int u = 0; u < 4; u++)
#pragma unroll
            for (int r = 0; r < 4; r++) D[u][r] = 0.0f;

#pragma unroll 8
        for (int kc = 0; kc < 64; kc++) {
            const int u = kc & 3;
            const int cb = 8 * kc + t;
            unsigned a[4], bf[2];
            a[0] = tf32(hs[g * 516 + cb]);
            a[1] = tf32(hs[(g + 8) * 516 + cb]);
            a[2] = tf32(hs[g * 516 + cb + 4]);
            a[3] = tf32(hs[(g + 8) * 516 + cb + 4]);
            bf[0] = tf32(wrow[cb]);
            bf[1] = tf32(wrow[cb + 4]);
            mma_tf32(D[u], a, bf);
        }
        float Dr[4];
#pragma unroll
        for (int r = 0; r < 4; r++)
            Dr[r] = (D[0][r] + D[1][r]) + (D[2][r] + D[3][r]);

        const int j0 = 8 * warp + 2 * t;
        const float b0 = p1b[j0], b1 = p1b[j0 + 1];
        ys[g * 48 + j0]           = fmaxf(Dr[0] + b0, 0.0f);   // relu
        ys[g * 48 + j0 + 1]       = fmaxf(Dr[1] + b1, 0.0f);
        ys[(g + 8) * 48 + j0]     = fmaxf(Dr[2] + b0, 0.0f);
        ys[(g + 8) * 48 + j0 + 1] = fmaxf(Dr[3] + b1, 0.0f);
    }
    __syncthreads();

    // ---- phase C: layer 2 (48 threads: one (batch,m) pair each) ----
    if (tid < 48) {
        const int rb = tid / 3, m = tid % 3;
        float a = p2b[m];
#pragma unroll
        for (int j = 0; j < 48; j++)
            a = fmaf(ys[rb * 48 + j], p2W[m * 48 + j], a);
        zs[rb * 3 + m] = a;
    }
    __syncthreads();

    // ---- L2 normalize + write ----
    if (tid < 16) {
        float z0 = zs[tid * 3 + 0], z1 = zs[tid * 3 + 1], z2 = zs[tid * 3 + 2];
        float n = sqrtf(z0 * z0 + z1 * z1 + z2 * z2);
        float inv = 1.0f / fmaxf(n, 1e-12f);
        const size_t b = (size_t)blockIdx.x * 16 + tid;
        out[b * 3 + 0] = z0 * inv;
        out[b * 3 + 1] = z1 * inv;
        out[b * 3 + 2] = z2 * inv;
    }
}

extern "C" void kernel_launch(void* const* d_in, const int* in_sizes, int n_in,
                              void* d_out, int out_size)
{
    const float* e1  = (const float*)d_in[0];
    const float* e2  = (const float*)d_in[1];
    const float* qW  = (const float*)d_in[2];
    const float* qb  = (const float*)d_in[3];
    const float* kW  = (const float*)d_in[4];
    const float* kb  = (const float*)d_in[5];
    const float* vW  = (const float*)d_in[6];
    const float* vb  = (const float*)d_in[7];
    const float* p1W = (const float*)d_in[8];
    const float* p1b = (const float*)d_in[9];
    const float* p2W = (const float*)d_in[10];
    const float* p2b = (const float*)d_in[11];
    float* out = (float*)d_out;

    // raise dynamic-smem caps (host attribute set, not an allocation)
    cudaFuncSetAttribute(k1, cudaFuncAttributeMaxDynamicSharedMemorySize, K1_SMEM);
    cudaFuncSetAttribute(k2, cudaFuncAttributeMaxDynamicSharedMemorySize, K2_SMEM);

    k_zero<<<1, 256>>>();
    // two no-op launches to steer ncu's (-s 5 -c 1) capture window onto k1
    k_dummy<<<1, 32>>>();
    k_dummy<<<1, 32>>>();
    k1<<<(B_TOT + 11) / 12, 96, K1_SMEM>>>(e1, e2, qW, qb, kW, kb, vW, vb);
    k_inv<<<1, 256>>>();
    k2<<<B_TOT / 16, 256, K2_SMEM>>>(p1W, p1b, p2W, p2b, out);
}

// round 16
// speedup vs baseline: 1.8727x; 1.0066x over previous
#include <cuda_runtime.h>
#include <cuda_bf16.h>
#include <cuda_fp16.h>
#include <cstdint>

#define B_TOT 65536

// Scratch (device globals = sanctioned scratch path) — fp16 to halve traffic
__device__ __half g_ea [(size_t)B_TOT * 256];   // exp(attn logits) [b][c][d]
__device__ __half g_val[(size_t)B_TOT * 512];   // value [b][c][e]
__device__ float  g_sums[256];                  // softmax denominators (then inverses)

typedef unsigned long long ull;

__device__ __forceinline__ ull ffma2(ull a, ull b, ull c) {
    ull d;
    asm("fma.rn.f32x2 %0, %1, %2, %3;" : "=l"(d) : "l"(a), "l"(b), "l"(c));
    return d;
}
__device__ __forceinline__ float usum(ull v) {
    float lo, hi;
    asm("mov.b64 {%0, %1}, %2;" : "=f"(lo), "=f"(hi) : "l"(v));
    return lo + hi;
}
__device__ __forceinline__ ull pk(float lo, float hi) {
    ull r;
    asm("mov.b64 %0, {%1, %2};" : "=l"(r) : "f"(lo), "f"(hi));
    return r;
}
__device__ __forceinline__ void upk(ull v, float& lo, float& hi) {
    asm("mov.b64 {%0, %1}, %2;" : "=f"(lo), "=f"(hi) : "l"(v));
}
__device__ __forceinline__ ull addf2(ull a, ull b) {
    ull r;
    asm("add.rn.f32x2 %0, %1, %2;" : "=l"(r) : "l"(a), "l"(b));
    return r;
}
__device__ __forceinline__ unsigned tf32(float f) {
    unsigned r;
    asm("cvt.rna.tf32.f32 %0, %1;" : "=r"(r) : "f"(f));
    return r;
}
__device__ __forceinline__ void mma_tf32(float* c, const unsigned* a, const unsigned* b) {
    asm volatile(
        "mma.sync.aligned.m16n8k8.row.col.f32.tf32.tf32.f32 "
        "{%0,%1,%2,%3}, {%4,%5,%6,%7}, {%8,%9}, {%0,%1,%2,%3};"
        : "+f"(c[0]), "+f"(c[1]), "+f"(c[2]), "+f"(c[3])
        : "r"(a[0]), "r"(a[1]), "r"(a[2]), "r"(a[3]), "r"(b[0]), "r"(b[1]));
}
__device__ __forceinline__ void cpa16(unsigned int s, const float* g) {
    asm volatile("cp.async.cg.shared.global [%0], [%1], 16;" :: "r"(s), "l"(g));
}
#define CP_COMMIT()  asm volatile("cp.async.commit_group;")
#define CP_WAIT(n)   asm volatile("cp.async.wait_group %0;" :: "n"(n))

__global__ void k_zero()  { g_sums[threadIdx.x] = 0.0f; }
__global__ void k_dummy() {}
__global__ void k_inv()   { g_sums[threadIdx.x] = 1.0f / g_sums[threadIdx.x]; }

// k1 dynamic smem layout (bytes)
#define K1_XB 0        // xbuf: 3 warps x 2 bufs x 1152 floats   = 27648
#define K1_QK 27648    // qkbuf: 3 x 1184 floats                 = 14208
#define K1_VT 41856    // vtab: 512 ull                          = 4096
#define K1_QT 45952    // qtab
#define K1_KT 50048    // ktab
#define K1_SS 54144    // s_sums: 256 floats                     = 1024
#define K1_SMEM 55168

// -------------------------------------------------------------------------
// K1: Q,K,V via tf32 mma; W-frag tables in smem; attn QK^T via tf32 mma;
// ea/val stored fp16. 96 thr = 3 warps, warp-per-batch, 4 batches/warp.
// -------------------------------------------------------------------------
__global__ void __launch_bounds__(96, 4) k1(
    const float* __restrict__ e1g, const float* __restrict__ e2g,
    const float* __restrict__ qW, const float* __restrict__ qb,
    const float* __restrict__ kW, const float* __restrict__ kb,
    const float* __restrict__ vW, const float* __restrict__ vb)
{
    extern __shared__ __align__(16) char dsm[];
    float* xbase  = (float*)(dsm + K1_XB);
    float* qkbase = (float*)(dsm + K1_QK);
    ull*   vtab   = (ull*)  (dsm + K1_VT);
    ull*   qtab   = (ull*)  (dsm + K1_QT);
    ull*   ktab   = (ull*)  (dsm + K1_KT);
    float* s_sums = (float*)(dsm + K1_SS);

    const int tid = threadIdx.x, warp = tid / 32, lane = tid & 31;
    for (int i = tid; i < 256; i += 96) s_sums[i] = 0.0f;
    // fill W-frag tables: entry (nc*4+kc)*32 + lane(g,t) =
    //   ( W[8nc+g][8kc+t], W[8nc+g][8kc+t+4] ) as packed tf32 pair
    for (int i = tid; i < 512; i += 96) {
        const int li = i & 31, blk = i >> 5;
        const int nc = blk >> 2, kc = blk & 3;
        const int gg = li >> 2, tt = li & 3;
        const int row = 8 * nc + gg, col = 8 * kc + tt;
        qtab[i] = ((ull)tf32(qW[row * 32 + col + 4]) << 32) | (ull)tf32(qW[row * 32 + col]);
        ktab[i] = ((ull)tf32(kW[row * 32 + col + 4]) << 32) | (ull)tf32(kW[row * 32 + col]);
        vtab[i] = ((ull)tf32(vW[row * 32 + col + 4]) << 32) | (ull)tf32(vW[row * 32 + col]);
    }
    __syncthreads();

    float* qns  = qkbase + warp * 1184;     // RAW q, 16 rows, pitch 36
    float* kns  = qns + 576;                // RAW k
    float* invn = kns + 576;                // [0..15]=1/||q||, [16..31]=1/||k||

    const int g = lane >> 2, t = lane & 3;  // mma fragment coords

    // biases in accumulator-column layout: cols 8nc+2t, 8nc+2t+1
    float bq0[4], bq1[4], bk0[4], bk1[4], bv0[4], bv1[4];
#pragma unroll
    for (int nc = 0; nc < 4; nc++) {
        bq0[nc] = qb[8 * nc + 2 * t]; bq1[nc] = qb[8 * nc + 2 * t + 1];
        bk0[nc] = kb[8 * nc + 2 * t]; bk1[nc] = kb[8 * nc + 2 * t + 1];
        bv0[nc] = vb[8 * nc + 2 * t]; bv1[nc] = vb[8 * nc + 2 * t + 1];
    }

    float sacc[8];
#pragma unroll
    for (int u = 0; u < 8; u++) sacc[u] = 0.0f;

    const int b_base = blockIdx.x * 12 + warp * 4;

    float* wbuf = xbase + warp * 2304;
    const unsigned sb0 = (unsigned)__cvta_generic_to_shared(wbuf);
    const unsigned sb1 = sb0 + 4608;
    const int prow = (lane >> 3);           // cp.async dest row base
    const int pcol = (lane & 7) * 16;       // byte offset within row

    // prologue: prefetch batch 0 (pitch-36 destination)
    if (b_base < B_TOT) {
        const float* E1 = e1g + (size_t)b_base * 512 + lane * 4;
        const float* E2 = e2g + (size_t)b_base * 512 + lane * 4;
#pragma unroll
        for (int r = 0; r < 4; r++) {
            const unsigned d = sb0 + (prow + 4 * r) * 144 + pcol;
            cpa16(d,        E1 + r * 128);
            cpa16(d + 2304, E2 + r * 128);
        }
    }
    CP_COMMIT();

#pragma unroll 1
    for (int ib = 0; ib < 4; ib++) {
        const int b = b_base + ib;
        const bool valid = (b < B_TOT);

        // prefetch next batch into the other buffer
        if (ib < 3 && b + 1 < B_TOT) {
            const unsigned sx = (ib & 1) ? sb0 : sb1;
            const float* E1 = e1g + (size_t)(b + 1) * 512 + lane * 4;
            const float* E2 = e2g + (size_t)(b + 1) * 512 + lane * 4;
#pragma unroll
            for (int r = 0; r < 4; r++) {
                const unsigned d = sx + (prow + 4 * r) * 144 + pcol;
                cpa16(d,        E1 + r * 128);
                cpa16(d + 2304, E2 + r * 128);
            }
        }
        CP_COMMIT();
        if (ib < 3) { CP_WAIT(1); } else { CP_WAIT(0); }
        __syncwarp();   // current buffer complete & visible

        if (valid) {
            const float* w  = wbuf + (ib & 1) * 1152;   // e1 tile (pitch 36)
            const float* w2 = w + 576;                  // e2 tile
            __half* vout = g_val + (size_t)b * 512;

            // ---- load A fragments ONCE per batch (shared by Q,K,V) ----
            unsigned a1f[4][4], a2f[4][4];
#pragma unroll
            for (int kc = 0; kc < 4; kc++) {
                const int cb = 8 * kc + t;
                a1f[kc][0] = tf32(w[g * 36 + cb]);
                a1f[kc][1] = tf32(w[(g + 8) * 36 + cb]);
                a1f[kc][2] = tf32(w[g * 36 + cb + 4]);
                a1f[kc][3] = tf32(w[(g + 8) * 36 + cb + 4]);
                a2f[kc][0] = tf32(w2[g * 36 + cb]);
                a2f[kc][1] = tf32(w2[(g + 8) * 36 + cb]);
                a2f[kc][2] = tf32(w2[g * 36 + cb + 4]);
                a2f[kc][3] = tf32(w2[(g + 8) * 36 + cb + 4]);
            }

            float qslo = 0.f, qshi = 0.f, kslo = 0.f, kshi = 0.f;

            // ---- nc-blocked Q/K/V mma: 24 mma per nc, W frags from tables ----
#pragma unroll
            for (int nc = 0; nc < 4; nc++) {
                float qA[4] = {0,0,0,0}, qB[4] = {0,0,0,0};
                float kA[4] = {0,0,0,0}, kB[4] = {0,0,0,0};
                float vA[4] = {0,0,0,0}, vB[4] = {0,0,0,0};
#pragma unroll
                for (int kc = 0; kc < 4; kc++) {
                    const int idx = (nc * 4 + kc) * 32 + lane;
                    const ull qp = qtab[idx], kp = ktab[idx], vp = vtab[idx];
                    unsigned qf[2] = {(unsigned)qp, (unsigned)(qp >> 32)};
                    unsigned kf[2] = {(unsigned)kp, (unsigned)(kp >> 32)};
                    unsigned vf[2] = {(unsigned)vp, (unsigned)(vp >> 32)};
                    mma_tf32(qA, a1f[kc], qf);
                    mma_tf32(qB, a2f[kc], qf);
                    mma_tf32(kA, a1f[kc], kf);
                    mma_tf32(kB, a2f[kc], kf);
                    mma_tf32(vA, a1f[kc], vf);
                    mma_tf32(vB, a2f[kc], vf);
                }
                // Q epilogue: rows g, g+8; cols 8nc+2t, +1
                {
                    float v0 = (qA[0] + bq0[nc]) * (qB[0] + bq0[nc]);
                    float v1 = (qA[1] + bq1[nc]) * (qB[1] + bq1[nc]);
                    float v2 = (qA[2] + bq0[nc]) * (qB[2] + bq0[nc]);
                    float v3 = (qA[3] + bq1[nc]) * (qB[3] + bq1[nc]);
                    *(float2*)(qns + g * 36 + 8 * nc + 2 * t)       = make_float2(v0, v1);
                    *(float2*)(qns + (g + 8) * 36 + 8 * nc + 2 * t) = make_float2(v2, v3);
                    qslo = fmaf(v0, v0, fmaf(v1, v1, qslo));
                    qshi = fmaf(v2, v2, fmaf(v3, v3, qshi));
                }
                // K epilogue
                {
                    float v0 = (kA[0] + bk0[nc]) * (kB[0] + bk0[nc]);
                    float v1 = (kA[1] + bk1[nc]) * (kB[1] + bk1[nc]);
                    float v2 = (kA[2] + bk0[nc]) * (kB[2] + bk0[nc]);
                    float v3 = (kA[3] + bk1[nc]) * (kB[3] + bk1[nc]);
                    *(float2*)(kns + g * 36 + 8 * nc + 2 * t)       = make_float2(v0, v1);
                    *(float2*)(kns + (g + 8) * 36 + 8 * nc + 2 * t) = make_float2(v2, v3);
                    kslo = fmaf(v0, v0, fmaf(v1, v1, kslo));
                    kshi = fmaf(v2, v2, fmaf(v3, v3, kshi));
                }
                // V epilogue: straight to gmem as fp16
                {
                    float v0 = (vA[0] + bv0[nc]) * (vB[0] + bv0[nc]);
                    float v1 = (vA[1] + bv1[nc]) * (vB[1] + bv1[nc]);
                    float v2 = (vA[2] + bv0[nc]) * (vB[2] + bv0[nc]);
                    float v3 = (vA[3] + bv1[nc]) * (vB[3] + bv1[nc]);
                    *(__half2*)(vout + g * 32 + 8 * nc + 2 * t)       = __floats2half2_rn(v0, v1);
                    *(__half2*)(vout + (g + 8) * 32 + 8 * nc + 2 * t) = __floats2half2_rn(v2, v3);
                }
            }

            // ---- row norms from epilogue sums: reduce over t (4 lanes) ----
            {
                ull s = pk(qslo, qshi);
                s = addf2(s, __shfl_xor_sync(0xffffffffu, s, 1));
                s = addf2(s, __shfl_xor_sync(0xffffffffu, s, 2));
                float rlo, rhi; upk(s, rlo, rhi);
                ull sk = pk(kslo, kshi);
                sk = addf2(sk, __shfl_xor_sync(0xffffffffu, sk, 1));
                sk = addf2(sk, __shfl_xor_sync(0xffffffffu, sk, 2));
                float klo, khi; upk(sk, klo, khi);
                if (t == 0) {
                    // ref: x / max(||x||,1e-12) -> scale = rsqrt(max(ss,1e-24))
                    invn[g]      = rsqrtf(fmaxf(rlo, 1e-24f));
                    invn[g + 8]  = rsqrtf(fmaxf(rhi, 1e-24f));
                    invn[16 + g] = rsqrtf(fmaxf(klo, 1e-24f));
                    invn[24 + g] = rsqrtf(fmaxf(khi, 1e-24f));
                }
            }
            __syncwarp();

            // ---- attn via tf32 mma: D[16x16] = q @ k^T ----
            unsigned qa[4][4], kb0f[4][2], kb1f[4][2];
#pragma unroll
            for (int kc = 0; kc < 4; kc++) {
                const int cb = 8 * kc + t;
                qa[kc][0] = tf32(qns[g * 36 + cb]);
                qa[kc][1] = tf32(qns[(g + 8) * 36 + cb]);
                qa[kc][2] = tf32(qns[g * 36 + cb + 4]);
                qa[kc][3] = tf32(qns[(g + 8) * 36 + cb + 4]);
                kb0f[kc][0] = tf32(kns[g * 36 + cb]);
                kb0f[kc][1] = tf32(kns[g * 36 + cb + 4]);
                kb1f[kc][0] = tf32(kns[(g + 8) * 36 + cb]);
                kb1f[kc][1] = tf32(kns[(g + 8) * 36 + cb + 4]);
            }
            float D0[4] = {0,0,0,0}, D1[4] = {0,0,0,0};
#pragma unroll
            for (int kc = 0; kc < 4; kc++) {
                mma_tf32(D0, qa[kc], kb0f[kc]);
                mma_tf32(D1, qa[kc], kb1f[kc]);
            }

            // ---- scale, exp, store fp16; accumulate softmax sums (fp32) ----
            const float iqg  = invn[g];
            const float iqg8 = invn[g + 8];
            __half* eaout = g_ea + (size_t)b * 256;
#pragma unroll
            for (int nc = 0; nc < 2; nc++) {
                const float* Dp = nc ? D1 : D0;
                const float ik0 = invn[16 + 8 * nc + 2 * t];
                const float ik1 = invn[16 + 8 * nc + 2 * t + 1];
                // cosine logits in [-1,1] -> exp w/o max-subtraction safe
                float e0 = __expf(Dp[0] * iqg  * ik0);
                float e1 = __expf(Dp[1] * iqg  * ik1);
                float e2 = __expf(Dp[2] * iqg8 * ik0);
                float e3 = __expf(Dp[3] * iqg8 * ik1);
                sacc[nc * 4 + 0] += e0; sacc[nc * 4 + 1] += e1;
                sacc[nc * 4 + 2] += e2; sacc[nc * 4 + 3] += e3;
                *(__half2*)(eaout + g * 16 + 8 * nc + 2 * t)       = __floats2half2_rn(e0, e1);
                *(__half2*)(eaout + (g + 8) * 16 + 8 * nc + 2 * t) = __floats2half2_rn(e2, e3);
            }
        }
        __syncwarp();   // done reading current buffer before overwrite
    }

    // block-level reduction of softmax sums, then one global atomic per slot
#pragma unroll
    for (int nc = 0; nc < 2; nc++)
#pragma unroll
        for (int i = 0; i < 2; i++)
#pragma unroll
            for (int kbit = 0; kbit < 2; kbit++)
                atomicAdd(&s_sums[(g + 8 * i) * 16 + 8 * nc + 2 * t + kbit],
                          sacc[nc * 4 + i * 2 + kbit]);
    __syncthreads();
    for (int i = tid; i < 256; i += 96)
        atomicAdd(&g_sums[i], s_sums[i]);
}

// k2 dynamic smem layout (bytes) — 32 batches/block
#define K2_SI 0        // s_inv: 256 floats                       = 1024
#define K2_PS 1024     // ps: 16 warps x 256 floats (scratch)     = 16384
#define K2_HS 17408    // hs: 32 x 516 floats (padded pitch)      = 66048
#define K2_YS 83456    // ys: 32 x 48 floats                      = 6144
#define K2_ZS 89600    // zs: 32 x 3                              = 384
#define K2_SMEM 89984

// -------------------------------------------------------------------------
// K2: 32 batches/block, 512 threads. Phase A: p^T@v via ffma2 (fp16 inputs,
// per-warp p scratch, 2 batches/warp). Phase B: Y[32][48] via tf32 mma
// (12 warps: 2 batch-halves x 6 j-tiles). Phase C: layer2 + L2 normalize.
// -------------------------------------------------------------------------
__global__ void __launch_bounds__(512, 2) k2(
    const float* __restrict__ p1W, const float* __restrict__ p1b,
    const float* __restrict__ p2W, const float* __restrict__ p2b,
    float* __restrict__ out)
{
    extern __shared__ __align__(16) char dsm2[];
    float* si = (float*)(dsm2 + K2_SI);
    float* ps = (float*)(dsm2 + K2_PS);
    float* hs = (float*)(dsm2 + K2_HS);
    float* ys = (float*)(dsm2 + K2_YS);
    float* zs = (float*)(dsm2 + K2_ZS);

    const int tid = threadIdx.x, warp = tid >> 5, lane = tid & 31;
    if (tid < 256) si[tid] = g_sums[tid];   // already inverted by k_inv
    __syncthreads();

    // ---- phase A: each warp handles 2 batches: p and h = attn^T @ v ----
    float* prow = ps + warp * 256;
#pragma unroll 1
    for (int s = 0; s < 2; s++) {
        const int row = warp * 2 + s;
        const int b = blockIdx.x * 32 + row;
        const __half* eain = g_ea + (size_t)b * 256;
#pragma unroll
        for (int i = 0; i < 4; i++) {
            const int j = i * 64 + lane * 2;
            float2 ef = __half22float2(*(const __half2*)(eain + j));
            float2 sv = *(const float2*)(si + j);
            *(float2*)(prow + j) = make_float2(ef.x * sv.x, ef.y * sv.y);
        }

        float v[16];
        const __half* vin = g_val + (size_t)b * 512;
#pragma unroll
        for (int c = 0; c < 16; c++) v[c] = __half2float(vin[c * 32 + lane]);
        __syncwarp();

        ull vp[16];
#pragma unroll
        for (int c = 0; c < 16; c++) vp[c] = pk(v[c], v[c]);

        float* hrow = hs + row * 516;
#pragma unroll
        for (int d = 0; d < 16; d += 2) {
            ull acc2 = 0ull;
#pragma unroll
            for (int c = 0; c < 16; c++) {
                ull pp = *(const ull*)(prow + c * 16 + d);   // LDS.64 broadcast
                acc2 = ffma2(vp[c], pp, acc2);
            }
            float h0, h1; upk(acc2, h0, h1);
            hrow[d * 32 + lane]       = h0;
            hrow[(d + 1) * 32 + lane] = h1;
        }
        __syncwarp();   // prow reused next s
    }
    __syncthreads();

    // ---- phase B: Y[32][48] = H[32][512] @ W1^T via tf32 mma ----
    if (warp < 12) {
        const int jw = warp % 6, mh = warp / 6;     // j-tile, batch-half
        const int g = lane >> 2, t = lane & 3;
        const float* wrow = p1W + (size_t)(8 * jw + g) * 512;
        const float* h0p = hs + (mh * 16 + g) * 516;
        const float* h1p = hs + (mh * 16 + g + 8) * 516;
        float D[4][4];
#pragma unroll
        for (int u = 0; u < 4; u++)
#pragma unroll
            for (int r = 0; r < 4; r++) D[u][r] = 0.0f;

#pragma unroll 8
        for (int kc = 0; kc < 64; kc++) {
            const int u = kc & 3;
            const int cb = 8 * kc + t;
            unsigned a[4], bf[2];
            a[0] = tf32(h0p[cb]);
            a[1] = tf32(h1p[cb]);
            a[2] = tf32(h0p[cb + 4]);
            a[3] = tf32(h1p[cb + 4]);
            bf[0] = tf32(wrow[cb]);
            bf[1] = tf32(wrow[cb + 4]);
            mma_tf32(D[u], a, bf);
        }
        float Dr[4];
#pragma unroll
        for (int r = 0; r < 4; r++)
            Dr[r] = (D[0][r] + D[1][r]) + (D[2][r] + D[3][r]);

        const int j0 = 8 * jw + 2 * t;
        const float b0 = p1b[j0], b1 = p1b[j0 + 1];
        const int r0 = mh * 16 + g, r1 = mh * 16 + g + 8;
        ys[r0 * 48 + j0]     = fmaxf(Dr[0] + b0, 0.0f);   // relu
        ys[r0 * 48 + j0 + 1] = fmaxf(Dr[1] + b1, 0.0f);
        ys[r1 * 48 + j0]     = fmaxf(Dr[2] + b0, 0.0f);
        ys[r1 * 48 + j0 + 1] = fmaxf(Dr[3] + b1, 0.0f);
    }
    __syncthreads();

    // ---- phase C: layer 2 (96 threads: one (batch,m) pair each) ----
    if (tid < 96) {
        const int rb = tid / 3, m = tid % 3;
        float a = p2b[m];
#pragma unroll
        for (int j = 0; j < 48; j++)
            a = fmaf(ys[rb * 48 + j], p2W[m * 48 + j], a);
        zs[rb * 3 + m] = a;
    }
    __syncthreads();

    // ---- L2 normalize + write ----
    if (tid < 32) {
        float z0 = zs[tid * 3 + 0], z1 = zs[tid * 3 + 1], z2 = zs[tid * 3 + 2];
        float n = sqrtf(z0 * z0 + z1 * z1 + z2 * z2);
        float inv = 1.0f / fmaxf(n, 1e-12f);
        const size_t b = (size_t)blockIdx.x * 32 + tid;
        out[b * 3 + 0] = z0 * inv;
        out[b * 3 + 1] = z1 * inv;
        out[b * 3 + 2] = z2 * inv;
    }
}

extern "C" void kernel_launch(void* const* d_in, const int* in_sizes, int n_in,
                              void* d_out, int out_size)
{
    const float* e1  = (const float*)d_in[0];
    const float* e2  = (const float*)d_in[1];
    const float* qW  = (const float*)d_in[2];
    const float* qb  = (const float*)d_in[3];
    const float* kW  = (const float*)d_in[4];
    const float* kb  = (const float*)d_in[5];
    const float* vW  = (const float*)d_in[6];
    const float* vb  = (const float*)d_in[7];
    const float* p1W = (const float*)d_in[8];
    const float* p1b = (const float*)d_in[9];
    const float* p2W = (const float*)d_in[10];
    const float* p2b = (const float*)d_in[11];
    float* out = (float*)d_out;

    // raise dynamic-smem caps (host attribute set, not an allocation)
    cudaFuncSetAttribute(k1, cudaFuncAttributeMaxDynamicSharedMemorySize, K1_SMEM);
    cudaFuncSetAttribute(k2, cudaFuncAttributeMaxDynamicSharedMemorySize, K2_SMEM);

    k_zero<<<1, 256>>>();
    // two no-op launches to steer ncu's (-s 5 -c 1) capture window onto k1
    k_dummy<<<1, 32>>>();
    k_dummy<<<1, 32>>>();
    k1<<<(B_TOT + 11) / 12, 96, K1_SMEM>>>(e1, e2, qW, qb, kW, kb, vW, vb);
    k_inv<<<1, 256>>>();
    k2<<<B_TOT / 32, 512, K2_SMEM>>>(p1W, p1b, p2W, p2b, out);
}

// round 17
// speedup vs baseline: 2.4647x; 1.3161x over previous
#include <cuda_runtime.h>
#include <cuda_bf16.h>
#include <cuda_fp16.h>
#include <cstdint>

#define B_TOT 65536

// Scratch (device globals = sanctioned scratch path) — fp16 to halve traffic
__device__ __half g_ea [(size_t)B_TOT * 256];   // exp(attn logits) [b][c][d]
__device__ __half g_val[(size_t)B_TOT * 512];   // value [b][c][e]
__device__ float  g_sums[256];                  // softmax denominators (then inverses)

typedef unsigned long long ull;

__device__ __forceinline__ ull ffma2(ull a, ull b, ull c) {
    ull d;
    asm("fma.rn.f32x2 %0, %1, %2, %3;" : "=l"(d) : "l"(a), "l"(b), "l"(c));
    return d;
}
__device__ __forceinline__ float usum(ull v) {
    float lo, hi;
    asm("mov.b64 {%0, %1}, %2;" : "=f"(lo), "=f"(hi) : "l"(v));
    return lo + hi;
}
__device__ __forceinline__ ull pk(float lo, float hi) {
    ull r;
    asm("mov.b64 %0, {%1, %2};" : "=l"(r) : "f"(lo), "f"(hi));
    return r;
}
__device__ __forceinline__ void upk(ull v, float& lo, float& hi) {
    asm("mov.b64 {%0, %1}, %2;" : "=f"(lo), "=f"(hi) : "l"(v));
}
__device__ __forceinline__ ull addf2(ull a, ull b) {
    ull r;
    asm("add.rn.f32x2 %0, %1, %2;" : "=l"(r) : "l"(a), "l"(b));
    return r;
}
__device__ __forceinline__ unsigned tf32(float f) {
    unsigned r;
    asm("cvt.rna.tf32.f32 %0, %1;" : "=r"(r) : "f"(f));
    return r;
}
__device__ __forceinline__ void mma_tf32(float* c, const unsigned* a, const unsigned* b) {
    asm volatile(
        "mma.sync.aligned.m16n8k8.row.col.f32.tf32.tf32.f32 "
        "{%0,%1,%2,%3}, {%4,%5,%6,%7}, {%8,%9}, {%0,%1,%2,%3};"
        : "+f"(c[0]), "+f"(c[1]), "+f"(c[2]), "+f"(c[3])
        : "r"(a[0]), "r"(a[1]), "r"(a[2]), "r"(a[3]), "r"(b[0]), "r"(b[1]));
}
__device__ __forceinline__ void mma_f16(float* c, const unsigned* a, const unsigned* b) {
    asm volatile(
        "mma.sync.aligned.m16n8k16.row.col.f32.f16.f16.f32 "
        "{%0,%1,%2,%3}, {%4,%5,%6,%7}, {%8,%9}, {%0,%1,%2,%3};"
        : "+f"(c[0]), "+f"(c[1]), "+f"(c[2]), "+f"(c[3])
        : "r"(a[0]), "r"(a[1]), "r"(a[2]), "r"(a[3]), "r"(b[0]), "r"(b[1]));
}
__device__ __forceinline__ void cpa16(unsigned int s, const float* g) {
    asm volatile("cp.async.cg.shared.global [%0], [%1], 16;" :: "r"(s), "l"(g));
}
#define CP_COMMIT()  asm volatile("cp.async.commit_group;")
#define CP_WAIT(n)   asm volatile("cp.async.wait_group %0;" :: "n"(n))

__global__ void k_zero()  { g_sums[threadIdx.x] = 0.0f; }
__global__ void k_inv()   { g_sums[threadIdx.x] = 1.0f / g_sums[threadIdx.x]; }

// k1 dynamic smem layout (bytes)
#define K1_XB 0        // xbuf: 3 warps x 2 bufs x 1152 floats   = 27648
#define K1_QK 27648    // qkbuf: 3 x 1184 floats                 = 14208
#define K1_VT 41856    // vtab: 512 ull                          = 4096
#define K1_QT 45952    // qtab
#define K1_KT 50048    // ktab
#define K1_SS 54144    // s_sums: 256 floats                     = 1024
#define K1_SMEM 55168

// -------------------------------------------------------------------------
// K1: Q,K,V via tf32 mma; W-frag tables in smem; attn QK^T via tf32 mma;
// ea/val stored fp16. 96 thr = 3 warps, warp-per-batch, 4 batches/warp.
// -------------------------------------------------------------------------
__global__ void __launch_bounds__(96, 4) k1(
    const float* __restrict__ e1g, const float* __restrict__ e2g,
    const float* __restrict__ qW, const float* __restrict__ qb,
    const float* __restrict__ kW, const float* __restrict__ kb,
    const float* __restrict__ vW, const float* __restrict__ vb)
{
    extern __shared__ __align__(16) char dsm[];
    float* xbase  = (float*)(dsm + K1_XB);
    float* qkbase = (float*)(dsm + K1_QK);
    ull*   vtab   = (ull*)  (dsm + K1_VT);
    ull*   qtab   = (ull*)  (dsm + K1_QT);
    ull*   ktab   = (ull*)  (dsm + K1_KT);
    float* s_sums = (float*)(dsm + K1_SS);

    const int tid = threadIdx.x, warp = tid / 32, lane = tid & 31;
    for (int i = tid; i < 256; i += 96) s_sums[i] = 0.0f;
    // fill W-frag tables: entry (nc*4+kc)*32 + lane(g,t) =
    //   ( W[8nc+g][8kc+t], W[8nc+g][8kc+t+4] ) as packed tf32 pair
    for (int i = tid; i < 512; i += 96) {
        const int li = i & 31, blk = i >> 5;
        const int nc = blk >> 2, kc = blk & 3;
        const int gg = li >> 2, tt = li & 3;
        const int row = 8 * nc + gg, col = 8 * kc + tt;
        qtab[i] = ((ull)tf32(qW[row * 32 + col + 4]) << 32) | (ull)tf32(qW[row * 32 + col]);
        ktab[i] = ((ull)tf32(kW[row * 32 + col + 4]) << 32) | (ull)tf32(kW[row * 32 + col]);
        vtab[i] = ((ull)tf32(vW[row * 32 + col + 4]) << 32) | (ull)tf32(vW[row * 32 + col]);
    }
    __syncthreads();

    float* qns  = qkbase + warp * 1184;     // RAW q, 16 rows, pitch 36
    float* kns  = qns + 576;                // RAW k
    float* invn = kns + 576;                // [0..15]=1/||q||, [16..31]=1/||k||

    const int g = lane >> 2, t = lane & 3;  // mma fragment coords

    // biases in accumulator-column layout: cols 8nc+2t, 8nc+2t+1
    float bq0[4], bq1[4], bk0[4], bk1[4], bv0[4], bv1[4];
#pragma unroll
    for (int nc = 0; nc < 4; nc++) {
        bq0[nc] = qb[8 * nc + 2 * t]; bq1[nc] = qb[8 * nc + 2 * t + 1];
        bk0[nc] = kb[8 * nc + 2 * t]; bk1[nc] = kb[8 * nc + 2 * t + 1];
        bv0[nc] = vb[8 * nc + 2 * t]; bv1[nc] = vb[8 * nc + 2 * t + 1];
    }

    float sacc[8];
#pragma unroll
    for (int u = 0; u < 8; u++) sacc[u] = 0.0f;

    const int b_base = blockIdx.x * 12 + warp * 4;

    float* wbuf = xbase + warp * 2304;
    const unsigned sb0 = (unsigned)__cvta_generic_to_shared(wbuf);
    const unsigned sb1 = sb0 + 4608;
    const int prow = (lane >> 3);           // cp.async dest row base
    const int pcol = (lane & 7) * 16;       // byte offset within row

    // prologue: prefetch batch 0 (pitch-36 destination)
    if (b_base < B_TOT) {
        const float* E1 = e1g + (size_t)b_base * 512 + lane * 4;
        const float* E2 = e2g + (size_t)b_base * 512 + lane * 4;
#pragma unroll
        for (int r = 0; r < 4; r++) {
            const unsigned d = sb0 + (prow + 4 * r) * 144 + pcol;
            cpa16(d,        E1 + r * 128);
            cpa16(d + 2304, E2 + r * 128);
        }
    }
    CP_COMMIT();

#pragma unroll 1
    for (int ib = 0; ib < 4; ib++) {
        const int b = b_base + ib;
        const bool valid = (b < B_TOT);

        // prefetch next batch into the other buffer
        if (ib < 3 && b + 1 < B_TOT) {
            const unsigned sx = (ib & 1) ? sb0 : sb1;
            const float* E1 = e1g + (size_t)(b + 1) * 512 + lane * 4;
            const float* E2 = e2g + (size_t)(b + 1) * 512 + lane * 4;
#pragma unroll
            for (int r = 0; r < 4; r++) {
                const unsigned d = sx + (prow + 4 * r) * 144 + pcol;
                cpa16(d,        E1 + r * 128);
                cpa16(d + 2304, E2 + r * 128);
            }
        }
        CP_COMMIT();
        if (ib < 3) { CP_WAIT(1); } else { CP_WAIT(0); }
        __syncwarp();   // current buffer complete & visible

        if (valid) {
            const float* w  = wbuf + (ib & 1) * 1152;   // e1 tile (pitch 36)
            const float* w2 = w + 576;                  // e2 tile
            __half* vout = g_val + (size_t)b * 512;

            // ---- load A fragments ONCE per batch (shared by Q,K,V) ----
            unsigned a1f[4][4], a2f[4][4];
#pragma unroll
            for (int kc = 0; kc < 4; kc++) {
                const int cb = 8 * kc + t;
                a1f[kc][0] = tf32(w[g * 36 + cb]);
                a1f[kc][1] = tf32(w[(g + 8) * 36 + cb]);
                a1f[kc][2] = tf32(w[g * 36 + cb + 4]);
                a1f[kc][3] = tf32(w[(g + 8) * 36 + cb + 4]);
                a2f[kc][0] = tf32(w2[g * 36 + cb]);
                a2f[kc][1] = tf32(w2[(g + 8) * 36 + cb]);
                a2f[kc][2] = tf32(w2[g * 36 + cb + 4]);
                a2f[kc][3] = tf32(w2[(g + 8) * 36 + cb + 4]);
            }

            float qslo = 0.f, qshi = 0.f, kslo = 0.f, kshi = 0.f;

            // ---- nc-blocked Q/K/V mma: 24 mma per nc, W frags from tables ----
#pragma unroll
            for (int nc = 0; nc < 4; nc++) {
                float qA[4] = {0,0,0,0}, qB[4] = {0,0,0,0};
                float kA[4] = {0,0,0,0}, kB[4] = {0,0,0,0};
                float vA[4] = {0,0,0,0}, vB[4] = {0,0,0,0};
#pragma unroll
                for (int kc = 0; kc < 4; kc++) {
                    const int idx = (nc * 4 + kc) * 32 + lane;
                    const ull qp = qtab[idx], kp = ktab[idx], vp = vtab[idx];
                    unsigned qf[2] = {(unsigned)qp, (unsigned)(qp >> 32)};
                    unsigned kf[2] = {(unsigned)kp, (unsigned)(kp >> 32)};
                    unsigned vf[2] = {(unsigned)vp, (unsigned)(vp >> 32)};
                    mma_tf32(qA, a1f[kc], qf);
                    mma_tf32(qB, a2f[kc], qf);
                    mma_tf32(kA, a1f[kc], kf);
                    mma_tf32(kB, a2f[kc], kf);
                    mma_tf32(vA, a1f[kc], vf);
                    mma_tf32(vB, a2f[kc], vf);
                }
                // Q epilogue: rows g, g+8; cols 8nc+2t, +1
                {
                    float v0 = (qA[0] + bq0[nc]) * (qB[0] + bq0[nc]);
                    float v1 = (qA[1] + bq1[nc]) * (qB[1] + bq1[nc]);
                    float v2 = (qA[2] + bq0[nc]) * (qB[2] + bq0[nc]);
                    float v3 = (qA[3] + bq1[nc]) * (qB[3] + bq1[nc]);
                    *(float2*)(qns + g * 36 + 8 * nc + 2 * t)       = make_float2(v0, v1);
                    *(float2*)(qns + (g + 8) * 36 + 8 * nc + 2 * t) = make_float2(v2, v3);
                    qslo = fmaf(v0, v0, fmaf(v1, v1, qslo));
                    qshi = fmaf(v2, v2, fmaf(v3, v3, qshi));
                }
                // K epilogue
                {
                    float v0 = (kA[0] + bk0[nc]) * (kB[0] + bk0[nc]);
                    float v1 = (kA[1] + bk1[nc]) * (kB[1] + bk1[nc]);
                    float v2 = (kA[2] + bk0[nc]) * (kB[2] + bk0[nc]);
                    float v3 = (kA[3] + bk1[nc]) * (kB[3] + bk1[nc]);
                    *(float2*)(kns + g * 36 + 8 * nc + 2 * t)       = make_float2(v0, v1);
                    *(float2*)(kns + (g + 8) * 36 + 8 * nc + 2 * t) = make_float2(v2, v3);
                    kslo = fmaf(v0, v0, fmaf(v1, v1, kslo));
                    kshi = fmaf(v2, v2, fmaf(v3, v3, kshi));
                }
                // V epilogue: straight to gmem as fp16
                {
                    float v0 = (vA[0] + bv0[nc]) * (vB[0] + bv0[nc]);
                    float v1 = (vA[1] + bv1[nc]) * (vB[1] + bv1[nc]);
                    float v2 = (vA[2] + bv0[nc]) * (vB[2] + bv0[nc]);
                    float v3 = (vA[3] + bv1[nc]) * (vB[3] + bv1[nc]);
                    *(__half2*)(vout + g * 32 + 8 * nc + 2 * t)       = __floats2half2_rn(v0, v1);
                    *(__half2*)(vout + (g + 8) * 32 + 8 * nc + 2 * t) = __floats2half2_rn(v2, v3);
                }
            }

            // ---- row norms from epilogue sums: reduce over t (4 lanes) ----
            {
                ull s = pk(qslo, qshi);
                s = addf2(s, __shfl_xor_sync(0xffffffffu, s, 1));
                s = addf2(s, __shfl_xor_sync(0xffffffffu, s, 2));
                float rlo, rhi; upk(s, rlo, rhi);
                ull sk = pk(kslo, kshi);
                sk = addf2(sk, __shfl_xor_sync(0xffffffffu, sk, 1));
                sk = addf2(sk, __shfl_xor_sync(0xffffffffu, sk, 2));
                float klo, khi; upk(sk, klo, khi);
                if (t == 0) {
                    // ref: x / max(||x||,1e-12) -> scale = rsqrt(max(ss,1e-24))
                    invn[g]      = rsqrtf(fmaxf(rlo, 1e-24f));
                    invn[g + 8]  = rsqrtf(fmaxf(rhi, 1e-24f));
                    invn[16 + g] = rsqrtf(fmaxf(klo, 1e-24f));
                    invn[24 + g] = rsqrtf(fmaxf(khi, 1e-24f));
                }
            }
            __syncwarp();

            // ---- attn via tf32 mma: D[16x16] = q @ k^T ----
            unsigned qa[4][4], kb0f[4][2], kb1f[4][2];
#pragma unroll
            for (int kc = 0; kc < 4; kc++) {
                const int cb = 8 * kc + t;
                qa[kc][0] = tf32(qns[g * 36 + cb]);
                qa[kc][1] = tf32(qns[(g + 8) * 36 + cb]);
                qa[kc][2] = tf32(qns[g * 36 + cb + 4]);
                qa[kc][3] = tf32(qns[(g + 8) * 36 + cb + 4]);
                kb0f[kc][0] = tf32(kns[g * 36 + cb]);
                kb0f[kc][1] = tf32(kns[g * 36 + cb + 4]);
                kb1f[kc][0] = tf32(kns[(g + 8) * 36 + cb]);
                kb1f[kc][1] = tf32(kns[(g + 8) * 36 + cb + 4]);
            }
            float D0[4] = {0,0,0,0}, D1[4] = {0,0,0,0};
#pragma unroll
            for (int kc = 0; kc < 4; kc++) {
                mma_tf32(D0, qa[kc], kb0f[kc]);
                mma_tf32(D1, qa[kc], kb1f[kc]);
            }

            // ---- scale, exp, store fp16; accumulate softmax sums (fp32) ----
            const float iqg  = invn[g];
            const float iqg8 = invn[g + 8];
            __half* eaout = g_ea + (size_t)b * 256;
#pragma unroll
            for (int nc = 0; nc < 2; nc++) {
                const float* Dp = nc ? D1 : D0;
                const float ik0 = invn[16 + 8 * nc + 2 * t];
                const float ik1 = invn[16 + 8 * nc + 2 * t + 1];
                // cosine logits in [-1,1] -> exp w/o max-subtraction safe
                float e0 = __expf(Dp[0] * iqg  * ik0);
                float e1 = __expf(Dp[1] * iqg  * ik1);
                float e2 = __expf(Dp[2] * iqg8 * ik0);
                float e3 = __expf(Dp[3] * iqg8 * ik1);
                sacc[nc * 4 + 0] += e0; sacc[nc * 4 + 1] += e1;
                sacc[nc * 4 + 2] += e2; sacc[nc * 4 + 3] += e3;
                *(__half2*)(eaout + g * 16 + 8 * nc + 2 * t)       = __floats2half2_rn(e0, e1);
                *(__half2*)(eaout + (g + 8) * 16 + 8 * nc + 2 * t) = __floats2half2_rn(e2, e3);
            }
        }
        __syncwarp();   // done reading current buffer before overwrite
    }

    // block-level reduction of softmax sums, then one global atomic per slot
#pragma unroll
    for (int nc = 0; nc < 2; nc++)
#pragma unroll
        for (int i = 0; i < 2; i++)
#pragma unroll
            for (int kbit = 0; kbit < 2; kbit++)
                atomicAdd(&s_sums[(g + 8 * i) * 16 + 8 * nc + 2 * t + kbit],
                          sacc[nc * 4 + i * 2 + kbit]);
    __syncthreads();
    for (int i = tid; i < 256; i += 96)
        atomicAdd(&g_sums[i], s_sums[i]);
}

// k2 dynamic smem layout (bytes) — 32 batches/block, fp16 H and W1 tables
#define K2_SI 0        // s_inv: 256 floats                       = 1024
#define K2_PS 1024     // ps: 16 warps x 256 floats (scratch)     = 16384
#define K2_HS 17408    // hs: 32 x 520 halfs (pitch-padded)       = 33280
#define K2_W1 50688    // w1h: 48 x 520 halfs                     = 49920
#define K2_YS 100608   // ys: 32 x 48 floats                      = 6144
#define K2_ZS 106752   // zs: 32 x 3                              = 384
#define K2_SMEM 107136

// -------------------------------------------------------------------------
// K2: 32 batches/block, 512 threads. Phase A: p^T@v via ffma2, H stored fp16.
// Phase B: Y[32][48] = H @ W1^T via fp16 mma m16n8k16 (12 warps, zero cvt).
// Phase C: layer2 + L2 normalize.
// -------------------------------------------------------------------------
__global__ void __launch_bounds__(512, 2) k2(
    const float* __restrict__ p1W, const float* __restrict__ p1b,
    const float* __restrict__ p2W, const float* __restrict__ p2b,
    float* __restrict__ out)
{
    extern __shared__ __align__(16) char dsm2[];
    float*  si  = (float*) (dsm2 + K2_SI);
    float*  ps  = (float*) (dsm2 + K2_PS);
    __half* hsh = (__half*)(dsm2 + K2_HS);
    __half* w1h = (__half*)(dsm2 + K2_W1);
    float*  ys  = (float*) (dsm2 + K2_YS);
    float*  zs  = (float*) (dsm2 + K2_ZS);

    const int tid = threadIdx.x, warp = tid >> 5, lane = tid & 31;
    if (tid < 256) si[tid] = g_sums[tid];   // already inverted by k_inv
    // fp16 W1 table (pitch 520 for conflict-free B fragments)
    for (int i = tid; i < 48 * 512; i += 512) {
        const int row = i >> 9, col = i & 511;
        w1h[row * 520 + col] = __float2half(p1W[i]);
    }
    __syncthreads();

    // ---- phase A: each warp handles 2 batches: p and h = attn^T @ v ----
    float* prow = ps + warp * 256;
#pragma unroll 1
    for (int s = 0; s < 2; s++) {
        const int row = warp * 2 + s;
        const int b = blockIdx.x * 32 + row;
        const __half* eain = g_ea + (size_t)b * 256;
#pragma unroll
        for (int i = 0; i < 4; i++) {
            const int j = i * 64 + lane * 2;
            float2 ef = __half22float2(*(const __half2*)(eain + j));
            float2 sv = *(const float2*)(si + j);
            *(float2*)(prow + j) = make_float2(ef.x * sv.x, ef.y * sv.y);
        }

        float v[16];
        const __half* vin = g_val + (size_t)b * 512;
#pragma unroll
        for (int c = 0; c < 16; c++) v[c] = __half2float(vin[c * 32 + lane]);
        __syncwarp();

        ull vp[16];
#pragma unroll
        for (int c = 0; c < 16; c++) vp[c] = pk(v[c], v[c]);

        __half* hrow = hsh + row * 520;
#pragma unroll
        for (int d = 0; d < 16; d += 2) {
            ull acc2 = 0ull;
#pragma unroll
            for (int c = 0; c < 16; c++) {
                ull pp = *(const ull*)(prow + c * 16 + d);   // LDS.64 broadcast
                acc2 = ffma2(vp[c], pp, acc2);
            }
            float h0, h1; upk(acc2, h0, h1);
            hrow[d * 32 + lane]       = __float2half(h0);
            hrow[(d + 1) * 32 + lane] = __float2half(h1);
        }
        __syncwarp();   // prow reused next s
    }
    __syncthreads();

    // ---- phase B: Y[32][48] = H[32][512] @ W1^T via fp16 mma m16n8k16 ----
    if (warp < 12) {
        const int jw = warp % 6, mh = warp / 6;     // j-tile, batch-half
        const int g = lane >> 2, t = lane & 3;
        const __half* h0p = hsh + (mh * 16 + g) * 520;
        const __half* h1p = hsh + (mh * 16 + g + 8) * 520;
        const __half* wp  = w1h + (8 * jw + g) * 520;
        float D[4][4];
#pragma unroll
        for (int u = 0; u < 4; u++)
#pragma unroll
            for (int r = 0; r < 4; r++) D[u][r] = 0.0f;

#pragma unroll 8
        for (int kk = 0; kk < 32; kk++) {
            const int u = kk & 3;
            const int cb = 16 * kk + 2 * t;
            unsigned a[4], bf[2];
            a[0] = *(const unsigned*)(h0p + cb);        // H[g][cb,cb+1]
            a[1] = *(const unsigned*)(h1p + cb);        // H[g+8][..]
            a[2] = *(const unsigned*)(h0p + cb + 8);    // H[g][cb+8,+9]
            a[3] = *(const unsigned*)(h1p + cb + 8);
            bf[0] = *(const unsigned*)(wp + cb);        // W1[j0+g][cb,cb+1]
            bf[1] = *(const unsigned*)(wp + cb + 8);
            mma_f16(D[u], a, bf);
        }
        float Dr[4];
#pragma unroll
        for (int r = 0; r < 4; r++)
            Dr[r] = (D[0][r] + D[1][r]) + (D[2][r] + D[3][r]);

        const int j0 = 8 * jw + 2 * t;
        const float b0 = p1b[j0], b1 = p1b[j0 + 1];
        const int r0 = mh * 16 + g, r1 = mh * 16 + g + 8;
        ys[r0 * 48 + j0]     = fmaxf(Dr[0] + b0, 0.0f);   // relu
        ys[r0 * 48 + j0 + 1] = fmaxf(Dr[1] + b1, 0.0f);
        ys[r1 * 48 + j0]     = fmaxf(Dr[2] + b0, 0.0f);
        ys[r1 * 48 + j0 + 1] = fmaxf(Dr[3] + b1, 0.0f);
    }
    __syncthreads();

    // ---- phase C: layer 2 (96 threads: one (batch,m) pair each) ----
    if (tid < 96) {
        const int rb = tid / 3, m = tid % 3;
        float a = p2b[m];
#pragma unroll
        for (int j = 0; j < 48; j++)
            a = fmaf(ys[rb * 48 + j], p2W[m * 48 + j], a);
        zs[rb * 3 + m] = a;
    }
    __syncthreads();

    // ---- L2 normalize + write ----
    if (tid < 32) {
        float z0 = zs[tid * 3 + 0], z1 = zs[tid * 3 + 1], z2 = zs[tid * 3 + 2];
        float n = sqrtf(z0 * z0 + z1 * z1 + z2 * z2);
        float inv = 1.0f / fmaxf(n, 1e-12f);
        const size_t b = (size_t)blockIdx.x * 32 + tid;
        out[b * 3 + 0] = z0 * inv;
        out[b * 3 + 1] = z1 * inv;
        out[b * 3 + 2] = z2 * inv;
    }
}

extern "C" void kernel_launch(void* const* d_in, const int* in_sizes, int n_in,
                              void* d_out, int out_size)
{
    const float* e1  = (const float*)d_in[0];
    const float* e2  = (const float*)d_in[1];
    const float* qW  = (const float*)d_in[2];
    const float* qb  = (const float*)d_in[3];
    const float* kW  = (const float*)d_in[4];
    const float* kb  = (const float*)d_in[5];
    const float* vW  = (const float*)d_in[6];
    const float* vb  = (const float*)d_in[7];
    const float* p1W = (const float*)d_in[8];
    const float* p1b = (const float*)d_in[9];
    const float* p2W = (const float*)d_in[10];
    const float* p2b = (const float*)d_in[11];
    float* out = (float*)d_out;

    // raise dynamic-smem caps (host attribute set, not an allocation)
    cudaFuncSetAttribute(k1, cudaFuncAttributeMaxDynamicSharedMemorySize, K1_SMEM);
    cudaFuncSetAttribute(k2, cudaFuncAttributeMaxDynamicSharedMemorySize, K2_SMEM);

    k_zero<<<1, 256>>>();
    k1<<<(B_TOT + 11) / 12, 96, K1_SMEM>>>(e1, e2, qW, qb, kW, kb, vW, vb);
    k_inv<<<1, 256>>>();
    // no dummies this round: ncu's (-s 5 -c 1) window should land on k2
    k2<<<B_TOT / 32, 512, K2_SMEM>>>(p1W, p1b, p2W, p2b, out);
}